// round 10
// baseline (speedup 1.0000x reference)
#include <cuda_runtime.h>

__device__ float g_scratch[6816768];
__device__ int g_cnt[2 * 4096];
__device__ int g_adj[2 * 4096 * 96];   // stores j*128 (premultiplied)

__device__ __forceinline__ float tanh_fast(float x) {
    float e = __expf(2.0f * x);
    return 1.0f - __fdividef(2.0f, e + 1.0f);
}
__device__ __forceinline__ float tanh_approx(float x) {
    float y; asm("tanh.approx.f32 %0, %1;" : "=f"(y) : "f"(x)); return y;
}

// ---------------- multi-job thin GEMM (64-row tiles, dbl-buffered, vec Ws) ----
struct GJob { const float* X; const float* W; const float* bias; float* out;
              const float* scale; int K; int NOUT; int flags; };
struct GJobs { GJob j[5]; };

template<int CN>
__device__ __forceinline__ void gemm_inner(float acc[4][8], const float Xs[32][68],
                                           const float Ws[32][132], int tx, int ty) {
#pragma unroll
    for (int k = 0; k < 32; k++) {
        float4 a = *(const float4*)&Xs[k][ty*4];
        float w[8];
        if (CN == 8) {
            *(float4*)&w[0] = *(const float4*)&Ws[k][tx*8];
            *(float4*)&w[4] = *(const float4*)&Ws[k][tx*8+4];
        } else if (CN == 4) {
            *(float4*)&w[0] = *(const float4*)&Ws[k][tx*4];
        } else {
            *(float2*)&w[0] = *(const float2*)&Ws[k][tx*2];
        }
#pragma unroll
        for (int c = 0; c < CN; c++) {
            acc[0][c] = fmaf(a.x, w[c], acc[0][c]);
            acc[1][c] = fmaf(a.y, w[c], acc[1][c]);
            acc[2][c] = fmaf(a.z, w[c], acc[2][c]);
            acc[3][c] = fmaf(a.w, w[c], acc[3][c]);
        }
    }
}

__global__ __launch_bounds__(256) void gemm_multi(GJobs jobs) {
    GJob jb = jobs.j[blockIdx.y];
    extern __shared__ float dsm[];
    float (*Xs)[32][68]  = (float(*)[32][68])dsm;
    float (*Ws)[32][132] = (float(*)[32][132])(dsm + 2*32*68);
    int tid = threadIdx.x, tx = tid & 15, ty = tid >> 4;
    int r0 = blockIdx.x * 64;
    float acc[4][8];
#pragma unroll
    for (int r = 0; r < 4; r++)
#pragma unroll
        for (int c = 0; c < 8; c++) acc[r][c] = 0.f;
    int cn = jb.NOUT >> 4;
    int bsel = r0 >> 9;
    int nw = jb.NOUT << 3;
    int nk = jb.K >> 5;

    float4 xv[2], wv[4];
    int xm2[2], xq[2];
#pragma unroll
    for (int i = 0; i < 2; i++) { int idx = tid + i*256; xm2[i] = idx >> 3; xq[i] = idx & 7; }

    auto prefetch = [&](int kk) {
#pragma unroll
        for (int i = 0; i < 2; i++) {
            float4 v = *(const float4*)(jb.X + (size_t)(r0 + xm2[i])*jb.K + kk + xq[i]*4);
            if (jb.flags & 4) {
                const float* sc = jb.scale + bsel*128 + kk + xq[i]*4;
                v.x *= sc[0]; v.y *= sc[1]; v.z *= sc[2]; v.w *= sc[3];
            }
            xv[i] = v;
        }
#pragma unroll
        for (int i = 0; i < 4; i++) {
            int idx = tid + i*256;
            if (idx < nw) {
                int n2 = idx >> 3, q = idx & 7;
                wv[i] = *(const float4*)(jb.W + (size_t)n2*jb.K + kk + q*4);
            }
        }
    };
    auto stash = [&](int buf) {
#pragma unroll
        for (int i = 0; i < 2; i++) {
            Xs[buf][xq[i]*4+0][xm2[i]] = xv[i].x;
            Xs[buf][xq[i]*4+1][xm2[i]] = xv[i].y;
            Xs[buf][xq[i]*4+2][xm2[i]] = xv[i].z;
            Xs[buf][xq[i]*4+3][xm2[i]] = xv[i].w;
        }
#pragma unroll
        for (int i = 0; i < 4; i++) {
            int idx = tid + i*256;
            if (idx < nw) {
                int n2 = idx >> 3, q = idx & 7;
                Ws[buf][q*4+0][n2] = wv[i].x;
                Ws[buf][q*4+1][n2] = wv[i].y;
                Ws[buf][q*4+2][n2] = wv[i].z;
                Ws[buf][q*4+3][n2] = wv[i].w;
            }
        }
    };

    prefetch(0);
    stash(0);
    __syncthreads();
    for (int kt = 0; kt < nk; kt++) {
        int buf = kt & 1;
        if (kt + 1 < nk) prefetch((kt + 1) << 5);
        if (cn == 8)      gemm_inner<8>(acc, Xs[buf], Ws[buf], tx, ty);
        else if (cn == 4) gemm_inner<4>(acc, Xs[buf], Ws[buf], tx, ty);
        else              gemm_inner<2>(acc, Xs[buf], Ws[buf], tx, ty);
        if (kt + 1 < nk) {
            stash(buf ^ 1);
            __syncthreads();
        }
    }
#pragma unroll
    for (int r = 0; r < 4; r++) {
        int row = r0 + ty*4 + r;
#pragma unroll
        for (int c = 0; c < 8; c++) {
            if (c >= cn) break;
            int n2 = tx*cn + c;
            float v = acc[r][c];
            if (jb.bias) v += jb.bias[n2];
            if (jb.flags & 1) v = fmaxf(v, 0.f);
            jb.out[(size_t)row*jb.NOUT + n2] = v;
        }
    }
}

// ---------------- adjacency precompute (single launch, both graphs) ---------
__global__ __launch_bounds__(128) void build_adj(
    const float* __restrict__ A, const float* __restrict__ Ac)
{
    __shared__ int lst[512];
    __shared__ int cnt;
    int bi = blockIdx.x, g = blockIdx.y;
    const float* M = (g == 0) ? A : Ac;
    int tid = threadIdx.x;
    if (tid == 0) cnt = 0;
    __syncthreads();
    float4 v = *(const float4*)(M + (size_t)bi*512 + tid*4);
    if (v.x != 0.f) lst[atomicAdd(&cnt,1)] = (tid*4+0)*128;
    if (v.y != 0.f) lst[atomicAdd(&cnt,1)] = (tid*4+1)*128;
    if (v.z != 0.f) lst[atomicAdd(&cnt,1)] = (tid*4+2)*128;
    if (v.w != 0.f) lst[atomicAdd(&cnt,1)] = (tid*4+3)*128;
    __syncthreads();
    int n = min(cnt, 96);
    if (tid == 0) g_cnt[g*4096 + bi] = n;
    for (int k = tid; k < n; k += 128) g_adj[(size_t)(g*4096 + bi)*96 + k] = lst[k];
}

// ---------------- sparse GIN aggregation -------------------------------------
__global__ __launch_bounds__(128) void gin_agg(
    const float* __restrict__ X, float* __restrict__ outA, float* __restrict__ outAc,
    const float* __restrict__ epsA, const float* __restrict__ epsAc)
{
    __shared__ int lst[96];
    int bi = blockIdx.x, g = blockIdx.y;
    float* out = (g == 0) ? outA : outAc;
    const float* ep = (g == 0) ? epsA : epsAc;
    int tid = threadIdx.x;
    int n = g_cnt[g*4096 + bi];
    if (tid < 96 && tid < n) lst[tid] = g_adj[(size_t)(g*4096 + bi)*96 + tid];
    __syncthreads();
    int b = bi >> 9;
    float acc = (1.0f + *ep) * X[(size_t)bi*128 + tid];
    const float* Xb = X + (size_t)(b << 9)*128 + tid;
    int k = 0;
    for (; k + 4 <= n; k += 4) {
        float v0 = Xb[lst[k]];
        float v1 = Xb[lst[k+1]];
        float v2 = Xb[lst[k+2]];
        float v3 = Xb[lst[k+3]];
        acc += (v0 + v1) + (v2 + v3);
    }
    for (; k < n; k++) acc += Xb[lst[k]];
    out[(size_t)bi*128 + tid] = acc;
}

// ---------------- topo combine ----------------------------------------------
__global__ void topo_combine(const float* __restrict__ Xh, const float* __restrict__ hA,
                             const float* __restrict__ hAC, const float* __restrict__ theta,
                             float* __restrict__ Xp)
{
    int idx = blockIdx.x*256 + threadIdx.x;
    int h = idx & 127;
    Xp[idx] = Xh[idx] + tanh_fast(hA[idx]*theta[2*h]) + tanh_fast(hAC[idx]*theta[2*h+1]);
}

// ---------------- fused flexible attention v4 (2 syncs per i) ----------------
__global__ __launch_bounds__(512) void attn_kernel(
    const float* __restrict__ ho, const float* __restrict__ h1,
    const float* __restrict__ wphi,
    const float* __restrict__ XA, const float* __restrict__ XAC,
    const float* __restrict__ wew, const float* __restrict__ web,
    float* __restrict__ alpha, float* __restrict__ bar)
{
    extern __shared__ float sm[];
    float* work  = sm;                // 512*33 = 16896 (raw tanh values)
    float* hos   = sm + 16896;        // 512
    float* wps   = hos + 512;         // 32
    float* part  = wps + 32;          // 16
    float* cpart = part + 16;         // 16*33 = 528
    float* ctxa  = cpart + 528;       // 16*32 = 512
    float* wews  = ctxa + 512;        // 128*33 = 4224
    float* webs  = wews + 4224;       // 128
    float* ss    = webs + 128;        // 512 (raw exp values)

    int tid = threadIdx.x;
    int lane = tid & 31, w = tid >> 5;
    int b = blockIdx.x >> 5;
    int i0 = (blockIdx.x & 31) << 4;

    float h1r[32];
    {
        const float4* src = (const float4*)(h1 + ((size_t)b*512 + tid)*32);
#pragma unroll
        for (int q = 0; q < 8; q++) {
            float4 v = src[q];
            h1r[q*4+0]=v.x; h1r[q*4+1]=v.y; h1r[q*4+2]=v.z; h1r[q*4+3]=v.w;
        }
    }
    hos[tid] = ho[((size_t)b*512 + i0)*32 + tid];
    if (tid < 32) wps[tid] = wphi[tid];
    if (tid < 128) webs[tid] = web[tid];
#pragma unroll
    for (int idx = tid; idx < 4096; idx += 512) {
        int hh = idx >> 5, d = idx & 31;
        wews[hh*33 + d] = wew[idx];
    }
    __syncthreads();

    for (int ii = 0; ii < 16; ii++) {
        float t[32];
        float s = 0.f;
        const float* hoi = hos + ii*32;
#pragma unroll
        for (int d = 0; d < 32; d++) {
            t[d] = tanh_approx(hoi[d] + h1r[d]);
            s = fmaf(wps[d], t[d], s);
        }
        float e = __expf(s);
        float es = e;
#pragma unroll
        for (int o = 16; o; o >>= 1) es += __shfl_xor_sync(0xffffffffu, es, o);
        if (lane == 0) part[w] = es;
        ss[tid] = e;
        float* wr = work + tid*33;
#pragma unroll
        for (int d = 0; d < 32; d++) wr[d] = t[d];
        __syncthreads();
        float tot = part[0];
#pragma unroll
        for (int q = 1; q < 16; q++) tot += part[q];
        float inv = 1.0f / tot;
        alpha[((size_t)(b*512 + i0 + ii))*512 + tid] = e * inv;
        {   // column reduce of e_j * t_jd (unscaled)
            float acc = 0.f;
            const float* base = work + (w*32)*33 + lane;
            const float* eb = ss + w*32;
#pragma unroll
            for (int k = 0; k < 32; k++) acc = fmaf(eb[k], base[k*33], acc);
            cpart[w*33 + lane] = acc;
        }
        __syncthreads();
        if (tid < 32) {
            float c = 0.f;
#pragma unroll
            for (int q = 0; q < 16; q++) c += cpart[q*33 + tid];
            ctxa[ii*32 + tid] = c * inv;
        }
    }
    __syncthreads();

#pragma unroll
    for (int r = 0; r < 4; r++) {
        int o = tid + r*512;
        int ii = o >> 7, hh = o & 127;
        size_t row = (size_t)b*512 + i0 + ii;
        float v = XA[row*128 + hh] + XAC[row*128 + hh] + webs[hh];
        const float* cw = wews + hh*33;
        const float* cx = ctxa + ii*32;
#pragma unroll
        for (int d = 0; d < 32; d++) v = fmaf(cx[d], cw[d], v);
        bar[row*128 + hh] = v;
    }
}

// ---------------- batched NN GEMM accumulate (R7 config) ---------------------
__global__ __launch_bounds__(256) void gemm_nn_acc(
    const float* __restrict__ al, const float* __restrict__ Bx, float* __restrict__ C)
{
    __shared__ float As[2][32][68];
    __shared__ float Bs[2][32][68];
    int b = blockIdx.z, m0 = blockIdx.x*64, n0 = blockIdx.y*64;
    int tid = threadIdx.x, tx = tid & 15, ty = tid >> 4;
    const float* Ab = al + (size_t)b*512*512;
    const float* Bb = Bx + (size_t)b*512*128;
    float acc[4][4];
#pragma unroll
    for (int r = 0; r < 4; r++)
#pragma unroll
        for (int c = 0; c < 4; c++) acc[r][c] = 0.f;

    float4 av[2], bv[2];
    auto prefetch = [&](int k0) {
#pragma unroll
        for (int i = 0; i < 2; i++) {
            int idx = tid + i*256;
            int mm = idx >> 3, q = idx & 7;
            av[i] = *(const float4*)(Ab + (size_t)(m0+mm)*512 + k0 + q*4);
        }
#pragma unroll
        for (int i = 0; i < 2; i++) {
            int idx = tid + i*256;
            int kk = idx >> 4, q = idx & 15;
            bv[i] = *(const float4*)(Bb + (size_t)(k0+kk)*128 + n0 + q*4);
        }
    };
    auto stash = [&](int buf) {
#pragma unroll
        for (int i = 0; i < 2; i++) {
            int idx = tid + i*256;
            int mm = idx >> 3, q = idx & 7;
            As[buf][q*4+0][mm]=av[i].x; As[buf][q*4+1][mm]=av[i].y;
            As[buf][q*4+2][mm]=av[i].z; As[buf][q*4+3][mm]=av[i].w;
        }
#pragma unroll
        for (int i = 0; i < 2; i++) {
            int idx = tid + i*256;
            int kk = idx >> 4, q = idx & 15;
            *(float4*)&Bs[buf][kk][q*4] = bv[i];
        }
    };

    prefetch(0);
    stash(0);
    __syncthreads();
    for (int kt = 0; kt < 16; kt++) {
        int buf = kt & 1;
        if (kt + 1 < 16) prefetch((kt + 1) << 5);
#pragma unroll
        for (int k = 0; k < 32; k++) {
            float a[4], bb[4];
            *(float4*)a  = *(const float4*)&As[buf][k][ty*4];
            *(float4*)bb = *(const float4*)&Bs[buf][k][tx*4];
#pragma unroll
            for (int r = 0; r < 4; r++)
#pragma unroll
                for (int c = 0; c < 4; c++) acc[r][c] = fmaf(a[r], bb[c], acc[r][c]);
        }
        if (kt + 1 < 16) {
            stash(buf ^ 1);
            __syncthreads();
        }
    }
    float* Cb = C + (size_t)b*512*128;
#pragma unroll
    for (int r = 0; r < 4; r++)
#pragma unroll
        for (int c = 0; c < 4; c++)
            Cb[(size_t)(m0+ty*4+r)*128 + n0+tx*4+c] += acc[r][c];
}

// ---------------- SE block ---------------------------------------------------
__global__ __launch_bounds__(128) void se_kernel(
    const float* __restrict__ bar, const float* __restrict__ w1,
    const float* __restrict__ b1, const float* __restrict__ w2,
    const float* __restrict__ b2, float* __restrict__ y2)
{
    __shared__ float pooled[128];
    __shared__ float y1s[32];
    int b = blockIdx.x, tid = threadIdx.x;
    const float* base = bar + (size_t)(b << 9)*128 + tid;
    float p = 0.f;
#pragma unroll 8
    for (int n = 0; n < 512; n++) p += base[n*128];
    pooled[tid] = p;
    __syncthreads();
    if (tid < 32) {
        float v = b1[tid];
        const float* wr = w1 + tid*128;
#pragma unroll 8
        for (int h = 0; h < 128; h++) v = fmaf(pooled[h], wr[h], v);
        y1s[tid] = fmaxf(v, 0.f);
    }
    __syncthreads();
    float v = b2[tid];
    const float* wr = w2 + tid*32;
#pragma unroll
    for (int r = 0; r < 32; r++) v = fmaf(y1s[r], wr[r], v);
    y2[b*128 + tid] = __fdividef(1.0f, 1.0f + __expf(-v));
}

// ---------------- head2: out[4096,3] -----------------------------------------
__global__ __launch_bounds__(192) void head2_kernel(
    const float* __restrict__ Hin, const float* __restrict__ W,
    const float* __restrict__ bias, float* __restrict__ out)
{
    __shared__ float Hs[64][68];
    __shared__ float Ws3[192];
    __shared__ float bs[3];
    int tid = threadIdx.x, r0 = blockIdx.x*64;
    for (int idx = tid; idx < 64*16; idx += 192) {
        int m2 = idx >> 4, q = idx & 15;
        *(float4*)&Hs[m2][q*4] = *(const float4*)(Hin + (size_t)(r0+m2)*64 + q*4);
    }
    if (tid < 192) Ws3[tid] = W[tid];
    if (tid < 3) bs[tid] = bias[tid];
    __syncthreads();
    int r = tid/3, o = tid%3;
    float acc = bs[o];
#pragma unroll 8
    for (int k = 0; k < 64; k++) acc = fmaf(Hs[r][k], Ws3[o*64+k], acc);
    out[(size_t)(r0+r)*3 + o] = acc;
}

// ---------------- host orchestration ----------------------------------------
extern "C" void kernel_launch(void* const* d_in, const int* in_sizes, int n_in,
                              void* d_out, int out_size) {
    const float* X       = (const float*)d_in[0];
    const float* A       = (const float*)d_in[1];
    const float* Ac      = (const float*)d_in[2];
    const float* embed_w = (const float*)d_in[3];
    const float* embed_b = (const float*)d_in[4];
    const float* topo_eps= (const float*)d_in[5];
    const float* topo_w  = (const float*)d_in[6];
    const float* topo_b  = (const float*)d_in[7];
    const float* theta   = (const float*)d_in[8];
    const float* gin_eps = (const float*)d_in[9];
    const float* gin_w   = (const float*)d_in[10];
    const float* gin_b   = (const float*)d_in[11];
    const float* wo      = (const float*)d_in[12];
    const float* w1      = (const float*)d_in[13];
    const float* wphi    = (const float*)d_in[14];
    const float* wy_w    = (const float*)d_in[15];
    const float* wy_b    = (const float*)d_in[16];
    const float* we_w    = (const float*)d_in[17];
    const float* we_b    = (const float*)d_in[18];
    const float* lin1_w  = (const float*)d_in[19];
    const float* lin1_b  = (const float*)d_in[20];
    const float* lin2_w  = (const float*)d_in[21];
    const float* lin2_b  = (const float*)d_in[22];
    const float* mlp_w   = (const float*)d_in[23];
    const float* mlp_b   = (const float*)d_in[24];
    const float* head1_w = (const float*)d_in[25];
    const float* head1_b = (const float*)d_in[26];
    const float* head2_w = (const float*)d_in[27];
    const float* head2_b = (const float*)d_in[28];
    float* out = (float*)d_out;

    float* S = nullptr;
    cudaGetSymbolAddress((void**)&S, g_scratch);
    const size_t BIG = 524288;
    float* Xh    = S;
    float* Xp    = S + 1*BIG;
    float* aggA  = S + 2*BIG;
    float* aggAc = S + 3*BIG;
    float* XAb   = S + 4*BIG;
    float* XACb  = S + 5*BIG;
    float* Xy    = S + 6*BIG;
    float* bar   = S + 7*BIG;
    float* hob   = S + 8*BIG;
    float* h1b   = hob + 131072;
    float* alphab= h1b + 131072;
    float* y2b   = alphab + 2097152;
    float* h64   = y2b + 1024;

    const int ATTN_SMEM = (16896 + 512 + 32 + 16 + 528 + 512 + 4224 + 128 + 512) * 4; // 93440
    const int GEMM_SMEM = (2*32*68 + 2*32*132) * 4;   // 51200
    cudaFuncSetAttribute(attn_kernel, cudaFuncAttributeMaxDynamicSharedMemorySize, ATTN_SMEM);
    cudaFuncSetAttribute(gemm_multi, cudaFuncAttributeMaxDynamicSharedMemorySize, GEMM_SMEM);

    build_adj<<<dim3(4096, 2), 128>>>(A, Ac);

    {   // embedding
        GJobs js{};
        js.j[0] = GJob{X, embed_w, embed_b, Xh, nullptr, 64, 128, 0};
        gemm_multi<<<dim3(64, 1), 256, GEMM_SMEM>>>(js);
    }
    gin_agg<<<dim3(4096, 2), 128>>>(Xh, aggA, aggAc, topo_eps, topo_eps);
    {
        GJobs js{};
        js.j[0] = GJob{aggA,  topo_w, topo_b, XAb,  nullptr, 128, 128, 1};
        js.j[1] = GJob{aggAc, topo_w, topo_b, XACb, nullptr, 128, 128, 1};
        gemm_multi<<<dim3(64, 2), 256, GEMM_SMEM>>>(js);
    }
    topo_combine<<<2048, 256>>>(Xh, XAb, XACb, theta, Xp);

    for (int l = 0; l < 3; l++) {
        gin_agg<<<dim3(4096, 2), 128>>>(Xp, aggA, aggAc,
                                        gin_eps + l*2, gin_eps + l*2 + 1);
        {
            GJobs js{};
            js.j[0] = GJob{aggA,  gin_w + (size_t)(l*2+0)*16384, gin_b + (l*2+0)*128, XAb,  nullptr, 128, 128, 1};
            js.j[1] = GJob{aggAc, gin_w + (size_t)(l*2+1)*16384, gin_b + (l*2+1)*128, XACb, nullptr, 128, 128, 1};
            js.j[2] = GJob{Xp, wy_w + (size_t)l*16384, wy_b + l*128, Xy, nullptr, 128, 128, 0};
            js.j[3] = GJob{Xp, wo + (size_t)l*4096, nullptr, hob, nullptr, 128, 32, 0};
            js.j[4] = GJob{Xp, w1 + (size_t)l*4096, nullptr, h1b, nullptr, 128, 32, 0};
            gemm_multi<<<dim3(64, 5), 256, GEMM_SMEM>>>(js);
        }
        attn_kernel<<<256, 512, ATTN_SMEM>>>(hob, h1b, wphi + l*32, XAb, XACb,
                                             we_w + (size_t)l*4096, we_b + l*128,
                                             alphab, bar);
        gemm_nn_acc<<<dim3(8, 2, 8), 256>>>(alphab, Xy, bar);
        se_kernel<<<8, 128>>>(bar, lin1_w + (size_t)l*4096, lin1_b + l*32,
                              lin2_w + (size_t)l*4096, lin2_b + l*128, y2b);
        {
            GJobs js{};
            js.j[0] = GJob{bar, mlp_w + (size_t)l*16384, mlp_b + l*128, Xp, y2b, 128, 128, 4};
            gemm_multi<<<dim3(64, 1), 256, GEMM_SMEM>>>(js);
        }
    }
    {
        GJobs js{};
        js.j[0] = GJob{Xp, head1_w, head1_b, h64, nullptr, 128, 64, 1};
        gemm_multi<<<dim3(64, 1), 256, GEMM_SMEM>>>(js);
    }
    head2_kernel<<<64, 192>>>(h64, head2_w, head2_b, out);
}

// round 11
// speedup vs baseline: 1.0982x; 1.0982x over previous
#include <cuda_runtime.h>

__device__ float g_scratch[6816768];
__device__ int g_cnt[2 * 4096];
__device__ int g_adj[2 * 4096 * 96];   // stores j*128 (premultiplied)

__device__ __forceinline__ float tanh_fast(float x) {
    float e = __expf(2.0f * x);
    return 1.0f - __fdividef(2.0f, e + 1.0f);
}
__device__ __forceinline__ float tanh_approx(float x) {
    float y; asm("tanh.approx.f32 %0, %1;" : "=f"(y) : "f"(x)); return y;
}

// ---------------- multi-job thin GEMM (64-row tiles, dbl-buffered) -----------
// Conflict-free Ws reads: thread tx owns cols [tx*4, tx*4+4) and (CN=8) [64+tx*4, ...).
struct GJob { const float* X; const float* W; const float* bias; float* out;
              const float* scale; int K; int NOUT; int flags; };
struct GJobs { GJob j[5]; };

template<int CN>
__device__ __forceinline__ void gemm_inner(float acc[4][8], const float Xs[32][68],
                                           const float Ws[32][132], int tx, int ty) {
#pragma unroll
    for (int k = 0; k < 32; k++) {
        float4 a = *(const float4*)&Xs[k][ty*4];
        float w[8];
        if (CN == 8) {
            *(float4*)&w[0] = *(const float4*)&Ws[k][tx*4];        // banks 0..31 once
            *(float4*)&w[4] = *(const float4*)&Ws[k][64 + tx*4];   // banks 0..31 once
        } else if (CN == 4) {
            *(float4*)&w[0] = *(const float4*)&Ws[k][tx*4];
        } else {
            *(float2*)&w[0] = *(const float2*)&Ws[k][tx*2];
        }
#pragma unroll
        for (int c = 0; c < CN; c++) {
            acc[0][c] = fmaf(a.x, w[c], acc[0][c]);
            acc[1][c] = fmaf(a.y, w[c], acc[1][c]);
            acc[2][c] = fmaf(a.z, w[c], acc[2][c]);
            acc[3][c] = fmaf(a.w, w[c], acc[3][c]);
        }
    }
}

__global__ __launch_bounds__(256) void gemm_multi(GJobs jobs) {
    GJob jb = jobs.j[blockIdx.y];
    extern __shared__ float dsm[];
    float (*Xs)[32][68]  = (float(*)[32][68])dsm;
    float (*Ws)[32][132] = (float(*)[32][132])(dsm + 2*32*68);
    int tid = threadIdx.x, tx = tid & 15, ty = tid >> 4;
    int r0 = blockIdx.x * 64;
    float acc[4][8];
#pragma unroll
    for (int r = 0; r < 4; r++)
#pragma unroll
        for (int c = 0; c < 8; c++) acc[r][c] = 0.f;
    int cn = jb.NOUT >> 4;
    int bsel = r0 >> 9;
    int nw = jb.NOUT << 3;
    int nk = jb.K >> 5;

    float4 xv[2], wv[4];
    int xm2[2], xq[2];
#pragma unroll
    for (int i = 0; i < 2; i++) { int idx = tid + i*256; xm2[i] = idx >> 3; xq[i] = idx & 7; }

    auto prefetch = [&](int kk) {
#pragma unroll
        for (int i = 0; i < 2; i++) {
            float4 v = *(const float4*)(jb.X + (size_t)(r0 + xm2[i])*jb.K + kk + xq[i]*4);
            if (jb.flags & 4) {
                const float* sc = jb.scale + bsel*128 + kk + xq[i]*4;
                v.x *= sc[0]; v.y *= sc[1]; v.z *= sc[2]; v.w *= sc[3];
            }
            xv[i] = v;
        }
#pragma unroll
        for (int i = 0; i < 4; i++) {
            int idx = tid + i*256;
            if (idx < nw) {
                int n2 = idx >> 3, q = idx & 7;
                wv[i] = *(const float4*)(jb.W + (size_t)n2*jb.K + kk + q*4);
            }
        }
    };
    auto stash = [&](int buf) {
#pragma unroll
        for (int i = 0; i < 2; i++) {
            Xs[buf][xq[i]*4+0][xm2[i]] = xv[i].x;
            Xs[buf][xq[i]*4+1][xm2[i]] = xv[i].y;
            Xs[buf][xq[i]*4+2][xm2[i]] = xv[i].z;
            Xs[buf][xq[i]*4+3][xm2[i]] = xv[i].w;
        }
#pragma unroll
        for (int i = 0; i < 4; i++) {
            int idx = tid + i*256;
            if (idx < nw) {
                int n2 = idx >> 3, q = idx & 7;
                Ws[buf][q*4+0][n2] = wv[i].x;
                Ws[buf][q*4+1][n2] = wv[i].y;
                Ws[buf][q*4+2][n2] = wv[i].z;
                Ws[buf][q*4+3][n2] = wv[i].w;
            }
        }
    };

    prefetch(0);
    stash(0);
    __syncthreads();
    for (int kt = 0; kt < nk; kt++) {
        int buf = kt & 1;
        if (kt + 1 < nk) prefetch((kt + 1) << 5);
        if (cn == 8)      gemm_inner<8>(acc, Xs[buf], Ws[buf], tx, ty);
        else if (cn == 4) gemm_inner<4>(acc, Xs[buf], Ws[buf], tx, ty);
        else              gemm_inner<2>(acc, Xs[buf], Ws[buf], tx, ty);
        if (kt + 1 < nk) {
            stash(buf ^ 1);
            __syncthreads();
        }
    }
#pragma unroll
    for (int r = 0; r < 4; r++) {
        int row = r0 + ty*4 + r;
#pragma unroll
        for (int c = 0; c < 8; c++) {
            if (c >= cn) break;
            int n2;
            if (cn == 8)      n2 = (c < 4) ? (tx*4 + c) : (64 + tx*4 + (c - 4));
            else if (cn == 4) n2 = tx*4 + c;
            else              n2 = tx*2 + c;
            float v = acc[r][c];
            if (jb.bias) v += jb.bias[n2];
            if (jb.flags & 1) v = fmaxf(v, 0.f);
            jb.out[(size_t)row*jb.NOUT + n2] = v;
        }
    }
}

// ---------------- adjacency precompute (single launch, both graphs) ---------
__global__ __launch_bounds__(128) void build_adj(
    const float* __restrict__ A, const float* __restrict__ Ac)
{
    __shared__ int lst[512];
    __shared__ int cnt;
    int bi = blockIdx.x, g = blockIdx.y;
    const float* M = (g == 0) ? A : Ac;
    int tid = threadIdx.x;
    if (tid == 0) cnt = 0;
    __syncthreads();
    float4 v = *(const float4*)(M + (size_t)bi*512 + tid*4);
    if (v.x != 0.f) lst[atomicAdd(&cnt,1)] = (tid*4+0)*128;
    if (v.y != 0.f) lst[atomicAdd(&cnt,1)] = (tid*4+1)*128;
    if (v.z != 0.f) lst[atomicAdd(&cnt,1)] = (tid*4+2)*128;
    if (v.w != 0.f) lst[atomicAdd(&cnt,1)] = (tid*4+3)*128;
    __syncthreads();
    int n = min(cnt, 96);
    if (tid == 0) g_cnt[g*4096 + bi] = n;
    for (int k = tid; k < n; k += 128) g_adj[(size_t)(g*4096 + bi)*96 + k] = lst[k];
}

// ---------------- sparse GIN aggregation -------------------------------------
__global__ __launch_bounds__(128) void gin_agg(
    const float* __restrict__ X, float* __restrict__ outA, float* __restrict__ outAc,
    const float* __restrict__ epsA, const float* __restrict__ epsAc)
{
    __shared__ int lst[96];
    int bi = blockIdx.x, g = blockIdx.y;
    float* out = (g == 0) ? outA : outAc;
    const float* ep = (g == 0) ? epsA : epsAc;
    int tid = threadIdx.x;
    int n = g_cnt[g*4096 + bi];
    if (tid < 96 && tid < n) lst[tid] = g_adj[(size_t)(g*4096 + bi)*96 + tid];
    __syncthreads();
    int b = bi >> 9;
    float acc = (1.0f + *ep) * X[(size_t)bi*128 + tid];
    const float* Xb = X + (size_t)(b << 9)*128 + tid;
    int k = 0;
    for (; k + 4 <= n; k += 4) {
        float v0 = Xb[lst[k]];
        float v1 = Xb[lst[k+1]];
        float v2 = Xb[lst[k+2]];
        float v3 = Xb[lst[k+3]];
        acc += (v0 + v1) + (v2 + v3);
    }
    for (; k < n; k++) acc += Xb[lst[k]];
    out[(size_t)bi*128 + tid] = acc;
}

// ---------------- topo combine ----------------------------------------------
__global__ void topo_combine(const float* __restrict__ Xh, const float* __restrict__ hA,
                             const float* __restrict__ hAC, const float* __restrict__ theta,
                             float* __restrict__ Xp)
{
    int idx = blockIdx.x*256 + threadIdx.x;
    int h = idx & 127;
    Xp[idx] = Xh[idx] + tanh_fast(hA[idx]*theta[2*h]) + tanh_fast(hAC[idx]*theta[2*h+1]);
}

// ---------------- fused flexible attention v4 ---------------------------------
__global__ __launch_bounds__(512) void attn_kernel(
    const float* __restrict__ ho, const float* __restrict__ h1,
    const float* __restrict__ wphi,
    const float* __restrict__ XA, const float* __restrict__ XAC,
    const float* __restrict__ wew, const float* __restrict__ web,
    float* __restrict__ alpha, float* __restrict__ bar)
{
    extern __shared__ float sm[];
    float* work  = sm;                // 512*33 = 16896 (raw tanh values)
    float* hos   = sm + 16896;        // 512
    float* wps   = hos + 512;         // 32
    float* part  = wps + 32;          // 16
    float* cpart = part + 16;         // 16*33 = 528
    float* ctxa  = cpart + 528;       // 16*32 = 512
    float* wews  = ctxa + 512;        // 128*33 = 4224
    float* webs  = wews + 4224;       // 128
    float* ss    = webs + 128;        // 512 (raw exp values)

    int tid = threadIdx.x;
    int lane = tid & 31, w = tid >> 5;
    int b = blockIdx.x >> 5;
    int i0 = (blockIdx.x & 31) << 4;

    float h1r[32];
    {
        const float4* src = (const float4*)(h1 + ((size_t)b*512 + tid)*32);
#pragma unroll
        for (int q = 0; q < 8; q++) {
            float4 v = src[q];
            h1r[q*4+0]=v.x; h1r[q*4+1]=v.y; h1r[q*4+2]=v.z; h1r[q*4+3]=v.w;
        }
    }
    hos[tid] = ho[((size_t)b*512 + i0)*32 + tid];
    if (tid < 32) wps[tid] = wphi[tid];
    if (tid < 128) webs[tid] = web[tid];
#pragma unroll
    for (int idx = tid; idx < 4096; idx += 512) {
        int hh = idx >> 5, d = idx & 31;
        wews[hh*33 + d] = wew[idx];
    }
    __syncthreads();

    for (int ii = 0; ii < 16; ii++) {
        float t[32];
        float s = 0.f;
        const float* hoi = hos + ii*32;
#pragma unroll
        for (int d = 0; d < 32; d++) {
            t[d] = tanh_approx(hoi[d] + h1r[d]);
            s = fmaf(wps[d], t[d], s);
        }
        float e = __expf(s);
        float es = e;
#pragma unroll
        for (int o = 16; o; o >>= 1) es += __shfl_xor_sync(0xffffffffu, es, o);
        if (lane == 0) part[w] = es;
        ss[tid] = e;
        float* wr = work + tid*33;
#pragma unroll
        for (int d = 0; d < 32; d++) wr[d] = t[d];
        __syncthreads();
        float tot = part[0];
#pragma unroll
        for (int q = 1; q < 16; q++) tot += part[q];
        float inv = 1.0f / tot;
        alpha[((size_t)(b*512 + i0 + ii))*512 + tid] = e * inv;
        {
            float acc = 0.f;
            const float* base = work + (w*32)*33 + lane;
            const float* eb = ss + w*32;
#pragma unroll
            for (int k = 0; k < 32; k++) acc = fmaf(eb[k], base[k*33], acc);
            cpart[w*33 + lane] = acc;
        }
        __syncthreads();
        if (tid < 32) {
            float c = 0.f;
#pragma unroll
            for (int q = 0; q < 16; q++) c += cpart[q*33 + tid];
            ctxa[ii*32 + tid] = c * inv;
        }
    }
    __syncthreads();

#pragma unroll
    for (int r = 0; r < 4; r++) {
        int o = tid + r*512;
        int ii = o >> 7, hh = o & 127;
        size_t row = (size_t)b*512 + i0 + ii;
        float v = XA[row*128 + hh] + XAC[row*128 + hh] + webs[hh];
        const float* cw = wews + hh*33;
        const float* cx = ctxa + ii*32;
#pragma unroll
        for (int d = 0; d < 32; d++) v = fmaf(cx[d], cw[d], v);
        bar[row*128 + hh] = v;
    }
}

// ---------------- batched NN GEMM accumulate ---------------------------------
__global__ __launch_bounds__(256) void gemm_nn_acc(
    const float* __restrict__ al, const float* __restrict__ Bx, float* __restrict__ C)
{
    __shared__ float As[2][32][68];
    __shared__ float Bs[2][32][68];
    int b = blockIdx.z, m0 = blockIdx.x*64, n0 = blockIdx.y*64;
    int tid = threadIdx.x, tx = tid & 15, ty = tid >> 4;
    const float* Ab = al + (size_t)b*512*512;
    const float* Bb = Bx + (size_t)b*512*128;
    float acc[4][4];
#pragma unroll
    for (int r = 0; r < 4; r++)
#pragma unroll
        for (int c = 0; c < 4; c++) acc[r][c] = 0.f;

    float4 av[2], bv[2];
    auto prefetch = [&](int k0) {
#pragma unroll
        for (int i = 0; i < 2; i++) {
            int idx = tid + i*256;
            int mm = idx >> 3, q = idx & 7;
            av[i] = *(const float4*)(Ab + (size_t)(m0+mm)*512 + k0 + q*4);
        }
#pragma unroll
        for (int i = 0; i < 2; i++) {
            int idx = tid + i*256;
            int kk = idx >> 4, q = idx & 15;
            bv[i] = *(const float4*)(Bb + (size_t)(k0+kk)*128 + n0 + q*4);
        }
    };
    auto stash = [&](int buf) {
#pragma unroll
        for (int i = 0; i < 2; i++) {
            int idx = tid + i*256;
            int mm = idx >> 3, q = idx & 7;
            As[buf][q*4+0][mm]=av[i].x; As[buf][q*4+1][mm]=av[i].y;
            As[buf][q*4+2][mm]=av[i].z; As[buf][q*4+3][mm]=av[i].w;
        }
#pragma unroll
        for (int i = 0; i < 2; i++) {
            int idx = tid + i*256;
            int kk = idx >> 4, q = idx & 15;
            *(float4*)&Bs[buf][kk][q*4] = bv[i];
        }
    };

    prefetch(0);
    stash(0);
    __syncthreads();
    for (int kt = 0; kt < 16; kt++) {
        int buf = kt & 1;
        if (kt + 1 < 16) prefetch((kt + 1) << 5);
#pragma unroll
        for (int k = 0; k < 32; k++) {
            float a[4], bb[4];
            *(float4*)a  = *(const float4*)&As[buf][k][ty*4];
            *(float4*)bb = *(const float4*)&Bs[buf][k][tx*4];
#pragma unroll
            for (int r = 0; r < 4; r++)
#pragma unroll
                for (int c = 0; c < 4; c++) acc[r][c] = fmaf(a[r], bb[c], acc[r][c]);
        }
        if (kt + 1 < 16) {
            stash(buf ^ 1);
            __syncthreads();
        }
    }
    float* Cb = C + (size_t)b*512*128;
#pragma unroll
    for (int r = 0; r < 4; r++)
#pragma unroll
        for (int c = 0; c < 4; c++)
            Cb[(size_t)(m0+ty*4+r)*128 + n0+tx*4+c] += acc[r][c];
}

// ---------------- SE block ---------------------------------------------------
__global__ __launch_bounds__(128) void se_kernel(
    const float* __restrict__ bar, const float* __restrict__ w1,
    const float* __restrict__ b1, const float* __restrict__ w2,
    const float* __restrict__ b2, float* __restrict__ y2)
{
    __shared__ float pooled[128];
    __shared__ float y1s[32];
    int b = blockIdx.x, tid = threadIdx.x;
    const float* base = bar + (size_t)(b << 9)*128 + tid;
    float p = 0.f;
#pragma unroll 8
    for (int n = 0; n < 512; n++) p += base[n*128];
    pooled[tid] = p;
    __syncthreads();
    if (tid < 32) {
        float v = b1[tid];
        const float* wr = w1 + tid*128;
#pragma unroll 8
        for (int h = 0; h < 128; h++) v = fmaf(pooled[h], wr[h], v);
        y1s[tid] = fmaxf(v, 0.f);
    }
    __syncthreads();
    float v = b2[tid];
    const float* wr = w2 + tid*32;
#pragma unroll
    for (int r = 0; r < 32; r++) v = fmaf(y1s[r], wr[r], v);
    y2[b*128 + tid] = __fdividef(1.0f, 1.0f + __expf(-v));
}

// ---------------- head2: out[4096,3] -----------------------------------------
__global__ __launch_bounds__(192) void head2_kernel(
    const float* __restrict__ Hin, const float* __restrict__ W,
    const float* __restrict__ bias, float* __restrict__ out)
{
    __shared__ float Hs[64][68];
    __shared__ float Ws3[192];
    __shared__ float bs[3];
    int tid = threadIdx.x, r0 = blockIdx.x*64;
    for (int idx = tid; idx < 64*16; idx += 192) {
        int m2 = idx >> 4, q = idx & 15;
        *(float4*)&Hs[m2][q*4] = *(const float4*)(Hin + (size_t)(r0+m2)*64 + q*4);
    }
    if (tid < 192) Ws3[tid] = W[tid];
    if (tid < 3) bs[tid] = bias[tid];
    __syncthreads();
    int r = tid/3, o = tid%3;
    float acc = bs[o];
#pragma unroll 8
    for (int k = 0; k < 64; k++) acc = fmaf(Hs[r][k], Ws3[o*64+k], acc);
    out[(size_t)(r0+r)*3 + o] = acc;
}

// ---------------- host orchestration ----------------------------------------
extern "C" void kernel_launch(void* const* d_in, const int* in_sizes, int n_in,
                              void* d_out, int out_size) {
    const float* X       = (const float*)d_in[0];
    const float* A       = (const float*)d_in[1];
    const float* Ac      = (const float*)d_in[2];
    const float* embed_w = (const float*)d_in[3];
    const float* embed_b = (const float*)d_in[4];
    const float* topo_eps= (const float*)d_in[5];
    const float* topo_w  = (const float*)d_in[6];
    const float* topo_b  = (const float*)d_in[7];
    const float* theta   = (const float*)d_in[8];
    const float* gin_eps = (const float*)d_in[9];
    const float* gin_w   = (const float*)d_in[10];
    const float* gin_b   = (const float*)d_in[11];
    const float* wo      = (const float*)d_in[12];
    const float* w1      = (const float*)d_in[13];
    const float* wphi    = (const float*)d_in[14];
    const float* wy_w    = (const float*)d_in[15];
    const float* wy_b    = (const float*)d_in[16];
    const float* we_w    = (const float*)d_in[17];
    const float* we_b    = (const float*)d_in[18];
    const float* lin1_w  = (const float*)d_in[19];
    const float* lin1_b  = (const float*)d_in[20];
    const float* lin2_w  = (const float*)d_in[21];
    const float* lin2_b  = (const float*)d_in[22];
    const float* mlp_w   = (const float*)d_in[23];
    const float* mlp_b   = (const float*)d_in[24];
    const float* head1_w = (const float*)d_in[25];
    const float* head1_b = (const float*)d_in[26];
    const float* head2_w = (const float*)d_in[27];
    const float* head2_b = (const float*)d_in[28];
    float* out = (float*)d_out;

    float* S = nullptr;
    cudaGetSymbolAddress((void**)&S, g_scratch);
    const size_t BIG = 524288;
    float* Xh    = S;
    float* Xp    = S + 1*BIG;
    float* aggA  = S + 2*BIG;
    float* aggAc = S + 3*BIG;
    float* XAb   = S + 4*BIG;
    float* XACb  = S + 5*BIG;
    float* Xy    = S + 6*BIG;
    float* bar   = S + 7*BIG;
    float* hob   = S + 8*BIG;
    float* h1b   = hob + 131072;
    float* alphab= h1b + 131072;
    float* y2b   = alphab + 2097152;
    float* h64   = y2b + 1024;

    const int ATTN_SMEM = (16896 + 512 + 32 + 16 + 528 + 512 + 4224 + 128 + 512) * 4; // 93440
    const int GEMM_SMEM = (2*32*68 + 2*32*132) * 4;   // 51200
    cudaFuncSetAttribute(attn_kernel, cudaFuncAttributeMaxDynamicSharedMemorySize, ATTN_SMEM);
    cudaFuncSetAttribute(gemm_multi, cudaFuncAttributeMaxDynamicSharedMemorySize, GEMM_SMEM);

    build_adj<<<dim3(4096, 2), 128>>>(A, Ac);

    {   // embedding
        GJobs js{};
        js.j[0] = GJob{X, embed_w, embed_b, Xh, nullptr, 64, 128, 0};
        gemm_multi<<<dim3(64, 1), 256, GEMM_SMEM>>>(js);
    }
    gin_agg<<<dim3(4096, 2), 128>>>(Xh, aggA, aggAc, topo_eps, topo_eps);
    {
        GJobs js{};
        js.j[0] = GJob{aggA,  topo_w, topo_b, XAb,  nullptr, 128, 128, 1};
        js.j[1] = GJob{aggAc, topo_w, topo_b, XACb, nullptr, 128, 128, 1};
        gemm_multi<<<dim3(64, 2), 256, GEMM_SMEM>>>(js);
    }
    topo_combine<<<2048, 256>>>(Xh, XAb, XACb, theta, Xp);

    for (int l = 0; l < 3; l++) {
        gin_agg<<<dim3(4096, 2), 128>>>(Xp, aggA, aggAc,
                                        gin_eps + l*2, gin_eps + l*2 + 1);
        {
            GJobs js{};
            js.j[0] = GJob{aggA,  gin_w + (size_t)(l*2+0)*16384, gin_b + (l*2+0)*128, XAb,  nullptr, 128, 128, 1};
            js.j[1] = GJob{aggAc, gin_w + (size_t)(l*2+1)*16384, gin_b + (l*2+1)*128, XACb, nullptr, 128, 128, 1};
            js.j[2] = GJob{Xp, wy_w + (size_t)l*16384, wy_b + l*128, Xy, nullptr, 128, 128, 0};
            js.j[3] = GJob{Xp, wo + (size_t)l*4096, nullptr, hob, nullptr, 128, 32, 0};
            js.j[4] = GJob{Xp, w1 + (size_t)l*4096, nullptr, h1b, nullptr, 128, 32, 0};
            gemm_multi<<<dim3(64, 5), 256, GEMM_SMEM>>>(js);
        }
        attn_kernel<<<256, 512, ATTN_SMEM>>>(hob, h1b, wphi + l*32, XAb, XACb,
                                             we_w + (size_t)l*4096, we_b + l*128,
                                             alphab, bar);
        gemm_nn_acc<<<dim3(8, 2, 8), 256>>>(alphab, Xy, bar);
        se_kernel<<<8, 128>>>(bar, lin1_w + (size_t)l*4096, lin1_b + l*32,
                              lin2_w + (size_t)l*4096, lin2_b + l*128, y2b);
        {
            GJobs js{};
            js.j[0] = GJob{bar, mlp_w + (size_t)l*16384, mlp_b + l*128, Xp, y2b, 128, 128, 4};
            gemm_multi<<<dim3(64, 1), 256, GEMM_SMEM>>>(js);
        }
    }
    {
        GJobs js{};
        js.j[0] = GJob{Xp, head1_w, head1_b, h64, nullptr, 128, 64, 1};
        gemm_multi<<<dim3(64, 1), 256, GEMM_SMEM>>>(js);
    }
    head2_kernel<<<64, 192>>>(h64, head2_w, head2_b, out);
}

// round 12
// speedup vs baseline: 1.1366x; 1.0349x over previous
#include <cuda_runtime.h>

__device__ float g_scratch[6816768];
__device__ int g_cnt[2 * 4096];
__device__ int g_adj[2 * 4096 * 96];   // stores j*128 (premultiplied)

__device__ __forceinline__ float tanh_fast(float x) {
    float e = __expf(2.0f * x);
    return 1.0f - __fdividef(2.0f, e + 1.0f);
}
__device__ __forceinline__ float tanh_approx(float x) {
    float y; asm("tanh.approx.f32 %0, %1;" : "=f"(y) : "f"(x)); return y;
}

// ---- packed f32x2 helpers (FFMA2) ------------------------------------------
__device__ __forceinline__ unsigned long long pack2(float x, float y) {
    unsigned long long r;
    asm("mov.b64 %0, {%1, %2};" : "=l"(r) : "f"(x), "f"(y));
    return r;
}
__device__ __forceinline__ unsigned long long ffma2(unsigned long long a,
                                                    unsigned long long b,
                                                    unsigned long long c) {
    unsigned long long d;
    asm("fma.rn.f32x2 %0, %1, %2, %3;" : "=l"(d) : "l"(a), "l"(b), "l"(c));
    return d;
}
__device__ __forceinline__ float2 unpack2(unsigned long long v) {
    float2 f;
    asm("mov.b64 {%0, %1}, %2;" : "=f"(f.x), "=f"(f.y) : "l"(v));
    return f;
}

// ---------------- multi-job thin GEMM (64-row tiles, dbl-buffered, FFMA2) ----
// Conflict-free Ws reads: thread tx owns cols [tx*4,tx*4+4) and (CN=8) [64+tx*4,..).
struct GJob { const float* X; const float* W; const float* bias; float* out;
              const float* scale; int K; int NOUT; int flags; };
struct GJobs { GJob j[5]; };

template<int CN>
__device__ __forceinline__ void gemm_inner(unsigned long long accp[4][4],
                                           const float Xs[32][68],
                                           const float Ws[32][132], int tx, int ty) {
#pragma unroll
    for (int k = 0; k < 32; k++) {
        float4 a = *(const float4*)&Xs[k][ty*4];
        unsigned long long pa[4];
        pa[0] = pack2(a.x, a.x); pa[1] = pack2(a.y, a.y);
        pa[2] = pack2(a.z, a.z); pa[3] = pack2(a.w, a.w);
        if (CN == 8) {
            ulonglong2 wA = *(const ulonglong2*)&Ws[k][tx*4];
            ulonglong2 wB = *(const ulonglong2*)&Ws[k][64 + tx*4];
#pragma unroll
            for (int r = 0; r < 4; r++) {
                accp[r][0] = ffma2(pa[r], wA.x, accp[r][0]);
                accp[r][1] = ffma2(pa[r], wA.y, accp[r][1]);
                accp[r][2] = ffma2(pa[r], wB.x, accp[r][2]);
                accp[r][3] = ffma2(pa[r], wB.y, accp[r][3]);
            }
        } else if (CN == 4) {
            ulonglong2 wA = *(const ulonglong2*)&Ws[k][tx*4];
#pragma unroll
            for (int r = 0; r < 4; r++) {
                accp[r][0] = ffma2(pa[r], wA.x, accp[r][0]);
                accp[r][1] = ffma2(pa[r], wA.y, accp[r][1]);
            }
        } else {
            unsigned long long wA = *(const unsigned long long*)&Ws[k][tx*2];
#pragma unroll
            for (int r = 0; r < 4; r++)
                accp[r][0] = ffma2(pa[r], wA, accp[r][0]);
        }
    }
}

__global__ __launch_bounds__(256) void gemm_multi(GJobs jobs) {
    GJob jb = jobs.j[blockIdx.y];
    extern __shared__ float dsm[];
    float (*Xs)[32][68]  = (float(*)[32][68])dsm;
    float (*Ws)[32][132] = (float(*)[32][132])(dsm + 2*32*68);
    int tid = threadIdx.x, tx = tid & 15, ty = tid >> 4;
    int r0 = blockIdx.x * 64;
    unsigned long long accp[4][4];
#pragma unroll
    for (int r = 0; r < 4; r++)
#pragma unroll
        for (int c = 0; c < 4; c++) accp[r][c] = 0ull;
    int cn = jb.NOUT >> 4;
    int bsel = r0 >> 9;
    int nw = jb.NOUT << 3;
    int nk = jb.K >> 5;

    float4 xv[2], wv[4];
    int xm2[2], xq[2];
#pragma unroll
    for (int i = 0; i < 2; i++) { int idx = tid + i*256; xm2[i] = idx >> 3; xq[i] = idx & 7; }

    auto prefetch = [&](int kk) {
#pragma unroll
        for (int i = 0; i < 2; i++) {
            float4 v = *(const float4*)(jb.X + (size_t)(r0 + xm2[i])*jb.K + kk + xq[i]*4);
            if (jb.flags & 4) {
                const float* sc = jb.scale + bsel*128 + kk + xq[i]*4;
                v.x *= sc[0]; v.y *= sc[1]; v.z *= sc[2]; v.w *= sc[3];
            }
            xv[i] = v;
        }
#pragma unroll
        for (int i = 0; i < 4; i++) {
            int idx = tid + i*256;
            if (idx < nw) {
                int n2 = idx >> 3, q = idx & 7;
                wv[i] = *(const float4*)(jb.W + (size_t)n2*jb.K + kk + q*4);
            }
        }
    };
    auto stash = [&](int buf) {
#pragma unroll
        for (int i = 0; i < 2; i++) {
            Xs[buf][xq[i]*4+0][xm2[i]] = xv[i].x;
            Xs[buf][xq[i]*4+1][xm2[i]] = xv[i].y;
            Xs[buf][xq[i]*4+2][xm2[i]] = xv[i].z;
            Xs[buf][xq[i]*4+3][xm2[i]] = xv[i].w;
        }
#pragma unroll
        for (int i = 0; i < 4; i++) {
            int idx = tid + i*256;
            if (idx < nw) {
                int n2 = idx >> 3, q = idx & 7;
                Ws[buf][q*4+0][n2] = wv[i].x;
                Ws[buf][q*4+1][n2] = wv[i].y;
                Ws[buf][q*4+2][n2] = wv[i].z;
                Ws[buf][q*4+3][n2] = wv[i].w;
            }
        }
    };

    prefetch(0);
    stash(0);
    __syncthreads();
    for (int kt = 0; kt < nk; kt++) {
        int buf = kt & 1;
        if (kt + 1 < nk) prefetch((kt + 1) << 5);
        if (cn == 8)      gemm_inner<8>(accp, Xs[buf], Ws[buf], tx, ty);
        else if (cn == 4) gemm_inner<4>(accp, Xs[buf], Ws[buf], tx, ty);
        else              gemm_inner<2>(accp, Xs[buf], Ws[buf], tx, ty);
        if (kt + 1 < nk) {
            stash(buf ^ 1);
            __syncthreads();
        }
    }
#pragma unroll
    for (int r = 0; r < 4; r++) {
        int row = r0 + ty*4 + r;
#pragma unroll
        for (int cp = 0; cp < 4; cp++) {
            if (cp >= (cn >> 1)) break;
            int n2;
            if (cn == 8)      n2 = (cp < 2) ? (tx*4 + cp*2) : (64 + tx*4 + (cp-2)*2);
            else if (cn == 4) n2 = tx*4 + cp*2;
            else              n2 = tx*2;
            float2 v = unpack2(accp[r][cp]);
            if (jb.bias) { v.x += jb.bias[n2]; v.y += jb.bias[n2+1]; }
            if (jb.flags & 1) { v.x = fmaxf(v.x, 0.f); v.y = fmaxf(v.y, 0.f); }
            jb.out[(size_t)row*jb.NOUT + n2]     = v.x;
            jb.out[(size_t)row*jb.NOUT + n2 + 1] = v.y;
        }
    }
}

// ---------------- adjacency precompute ---------------------------------------
__global__ __launch_bounds__(128) void build_adj(
    const float* __restrict__ A, const float* __restrict__ Ac)
{
    __shared__ int lst[512];
    __shared__ int cnt;
    int bi = blockIdx.x, g = blockIdx.y;
    const float* M = (g == 0) ? A : Ac;
    int tid = threadIdx.x;
    if (tid == 0) cnt = 0;
    __syncthreads();
    float4 v = *(const float4*)(M + (size_t)bi*512 + tid*4);
    if (v.x != 0.f) lst[atomicAdd(&cnt,1)] = (tid*4+0)*128;
    if (v.y != 0.f) lst[atomicAdd(&cnt,1)] = (tid*4+1)*128;
    if (v.z != 0.f) lst[atomicAdd(&cnt,1)] = (tid*4+2)*128;
    if (v.w != 0.f) lst[atomicAdd(&cnt,1)] = (tid*4+3)*128;
    __syncthreads();
    int n = min(cnt, 96);
    if (tid == 0) g_cnt[g*4096 + bi] = n;
    for (int k = tid; k < n; k += 128) g_adj[(size_t)(g*4096 + bi)*96 + k] = lst[k];
}

// ---------------- sparse GIN aggregation -------------------------------------
__global__ __launch_bounds__(128) void gin_agg(
    const float* __restrict__ X, float* __restrict__ outA, float* __restrict__ outAc,
    const float* __restrict__ epsA, const float* __restrict__ epsAc)
{
    __shared__ int lst[96];
    int bi = blockIdx.x, g = blockIdx.y;
    float* out = (g == 0) ? outA : outAc;
    const float* ep = (g == 0) ? epsA : epsAc;
    int tid = threadIdx.x;
    int n = g_cnt[g*4096 + bi];
    if (tid < 96 && tid < n) lst[tid] = g_adj[(size_t)(g*4096 + bi)*96 + tid];
    __syncthreads();
    int b = bi >> 9;
    float acc = (1.0f + *ep) * X[(size_t)bi*128 + tid];
    const float* Xb = X + (size_t)(b << 9)*128 + tid;
    int k = 0;
    for (; k + 4 <= n; k += 4) {
        float v0 = Xb[lst[k]];
        float v1 = Xb[lst[k+1]];
        float v2 = Xb[lst[k+2]];
        float v3 = Xb[lst[k+3]];
        acc += (v0 + v1) + (v2 + v3);
    }
    for (; k < n; k++) acc += Xb[lst[k]];
    out[(size_t)bi*128 + tid] = acc;
}

// ---------------- topo combine ----------------------------------------------
__global__ void topo_combine(const float* __restrict__ Xh, const float* __restrict__ hA,
                             const float* __restrict__ hAC, const float* __restrict__ theta,
                             float* __restrict__ Xp)
{
    int idx = blockIdx.x*256 + threadIdx.x;
    int h = idx & 127;
    Xp[idx] = Xh[idx] + tanh_fast(hA[idx]*theta[2*h]) + tanh_fast(hAC[idx]*theta[2*h+1]);
}

// ---------------- fused flexible attention v4 ---------------------------------
__global__ __launch_bounds__(512) void attn_kernel(
    const float* __restrict__ ho, const float* __restrict__ h1,
    const float* __restrict__ wphi,
    const float* __restrict__ XA, const float* __restrict__ XAC,
    const float* __restrict__ wew, const float* __restrict__ web,
    float* __restrict__ alpha, float* __restrict__ bar)
{
    extern __shared__ float sm[];
    float* work  = sm;                // 512*33 = 16896 (raw tanh values)
    float* hos   = sm + 16896;        // 512
    float* wps   = hos + 512;         // 32
    float* part  = wps + 32;          // 16
    float* cpart = part + 16;         // 16*33 = 528
    float* ctxa  = cpart + 528;       // 16*32 = 512
    float* wews  = ctxa + 512;        // 128*33 = 4224
    float* webs  = wews + 4224;       // 128
    float* ss    = webs + 128;        // 512 (raw exp values)

    int tid = threadIdx.x;
    int lane = tid & 31, w = tid >> 5;
    int b = blockIdx.x >> 5;
    int i0 = (blockIdx.x & 31) << 4;

    float h1r[32];
    {
        const float4* src = (const float4*)(h1 + ((size_t)b*512 + tid)*32);
#pragma unroll
        for (int q = 0; q < 8; q++) {
            float4 v = src[q];
            h1r[q*4+0]=v.x; h1r[q*4+1]=v.y; h1r[q*4+2]=v.z; h1r[q*4+3]=v.w;
        }
    }
    hos[tid] = ho[((size_t)b*512 + i0)*32 + tid];
    if (tid < 32) wps[tid] = wphi[tid];
    if (tid < 128) webs[tid] = web[tid];
#pragma unroll
    for (int idx = tid; idx < 4096; idx += 512) {
        int hh = idx >> 5, d = idx & 31;
        wews[hh*33 + d] = wew[idx];
    }
    __syncthreads();

    for (int ii = 0; ii < 16; ii++) {
        float t[32];
        float s = 0.f;
        const float* hoi = hos + ii*32;
#pragma unroll
        for (int d = 0; d < 32; d++) {
            t[d] = tanh_approx(hoi[d] + h1r[d]);
            s = fmaf(wps[d], t[d], s);
        }
        float e = __expf(s);
        float es = e;
#pragma unroll
        for (int o = 16; o; o >>= 1) es += __shfl_xor_sync(0xffffffffu, es, o);
        if (lane == 0) part[w] = es;
        ss[tid] = e;
        float* wr = work + tid*33;
#pragma unroll
        for (int d = 0; d < 32; d++) wr[d] = t[d];
        __syncthreads();
        float tot = part[0];
#pragma unroll
        for (int q = 1; q < 16; q++) tot += part[q];
        float inv = 1.0f / tot;
        alpha[((size_t)(b*512 + i0 + ii))*512 + tid] = e * inv;
        {
            float acc = 0.f;
            const float* base = work + (w*32)*33 + lane;
            const float* eb = ss + w*32;
#pragma unroll
            for (int k = 0; k < 32; k++) acc = fmaf(eb[k], base[k*33], acc);
            cpart[w*33 + lane] = acc;
        }
        __syncthreads();
        if (tid < 32) {
            float c = 0.f;
#pragma unroll
            for (int q = 0; q < 16; q++) c += cpart[q*33 + tid];
            ctxa[ii*32 + tid] = c * inv;
        }
    }
    __syncthreads();

#pragma unroll
    for (int r = 0; r < 4; r++) {
        int o = tid + r*512;
        int ii = o >> 7, hh = o & 127;
        size_t row = (size_t)b*512 + i0 + ii;
        float v = XA[row*128 + hh] + XAC[row*128 + hh] + webs[hh];
        const float* cw = wews + hh*33;
        const float* cx = ctxa + ii*32;
#pragma unroll
        for (int d = 0; d < 32; d++) v = fmaf(cx[d], cw[d], v);
        bar[row*128 + hh] = v;
    }
}

// ---------------- batched NN GEMM accumulate (FFMA2 inner) --------------------
__global__ __launch_bounds__(256) void gemm_nn_acc(
    const float* __restrict__ al, const float* __restrict__ Bx, float* __restrict__ C)
{
    __shared__ float As[2][32][68];
    __shared__ float Bs[2][32][68];
    int b = blockIdx.z, m0 = blockIdx.x*64, n0 = blockIdx.y*64;
    int tid = threadIdx.x, tx = tid & 15, ty = tid >> 4;
    const float* Ab = al + (size_t)b*512*512;
    const float* Bb = Bx + (size_t)b*512*128;
    unsigned long long accp[4][2];
#pragma unroll
    for (int r = 0; r < 4; r++) { accp[r][0] = 0ull; accp[r][1] = 0ull; }

    float4 av[2], bv[2];
    auto prefetch = [&](int k0) {
#pragma unroll
        for (int i = 0; i < 2; i++) {
            int idx = tid + i*256;
            int mm = idx >> 3, q = idx & 7;
            av[i] = *(const float4*)(Ab + (size_t)(m0+mm)*512 + k0 + q*4);
        }
#pragma unroll
        for (int i = 0; i < 2; i++) {
            int idx = tid + i*256;
            int kk = idx >> 4, q = idx & 15;
            bv[i] = *(const float4*)(Bb + (size_t)(k0+kk)*128 + n0 + q*4);
        }
    };
    auto stash = [&](int buf) {
#pragma unroll
        for (int i = 0; i < 2; i++) {
            int idx = tid + i*256;
            int mm = idx >> 3, q = idx & 7;
            As[buf][q*4+0][mm]=av[i].x; As[buf][q*4+1][mm]=av[i].y;
            As[buf][q*4+2][mm]=av[i].z; As[buf][q*4+3][mm]=av[i].w;
        }
#pragma unroll
        for (int i = 0; i < 2; i++) {
            int idx = tid + i*256;
            int kk = idx >> 4, q = idx & 15;
            *(float4*)&Bs[buf][kk][q*4] = bv[i];
        }
    };

    prefetch(0);
    stash(0);
    __syncthreads();
    for (int kt = 0; kt < 16; kt++) {
        int buf = kt & 1;
        if (kt + 1 < 16) prefetch((kt + 1) << 5);
#pragma unroll
        for (int k = 0; k < 32; k++) {
            float4 a = *(const float4*)&As[buf][k][ty*4];
            ulonglong2 wb = *(const ulonglong2*)&Bs[buf][k][tx*4];
            unsigned long long pa[4];
            pa[0] = pack2(a.x, a.x); pa[1] = pack2(a.y, a.y);
            pa[2] = pack2(a.z, a.z); pa[3] = pack2(a.w, a.w);
#pragma unroll
            for (int r = 0; r < 4; r++) {
                accp[r][0] = ffma2(pa[r], wb.x, accp[r][0]);
                accp[r][1] = ffma2(pa[r], wb.y, accp[r][1]);
            }
        }
        if (kt + 1 < 16) {
            stash(buf ^ 1);
            __syncthreads();
        }
    }
    float* Cb = C + (size_t)b*512*128;
#pragma unroll
    for (int r = 0; r < 4; r++)
#pragma unroll
        for (int cp = 0; cp < 2; cp++) {
            float2 v = unpack2(accp[r][cp]);
            size_t base = (size_t)(m0+ty*4+r)*128 + n0 + tx*4 + cp*2;
            Cb[base]     += v.x;
            Cb[base + 1] += v.y;
        }
}

// ---------------- SE block ---------------------------------------------------
__global__ __launch_bounds__(128) void se_kernel(
    const float* __restrict__ bar, const float* __restrict__ w1,
    const float* __restrict__ b1, const float* __restrict__ w2,
    const float* __restrict__ b2, float* __restrict__ y2)
{
    __shared__ float pooled[128];
    __shared__ float y1s[32];
    int b = blockIdx.x, tid = threadIdx.x;
    const float* base = bar + (size_t)(b << 9)*128 + tid;
    float p = 0.f;
#pragma unroll 8
    for (int n = 0; n < 512; n++) p += base[n*128];
    pooled[tid] = p;
    __syncthreads();
    if (tid < 32) {
        float v = b1[tid];
        const float* wr = w1 + tid*128;
#pragma unroll 8
        for (int h = 0; h < 128; h++) v = fmaf(pooled[h], wr[h], v);
        y1s[tid] = fmaxf(v, 0.f);
    }
    __syncthreads();
    float v = b2[tid];
    const float* wr = w2 + tid*32;
#pragma unroll
    for (int r = 0; r < 32; r++) v = fmaf(y1s[r], wr[r], v);
    y2[b*128 + tid] = __fdividef(1.0f, 1.0f + __expf(-v));
}

// ---------------- head2: out[4096,3] -----------------------------------------
__global__ __launch_bounds__(192) void head2_kernel(
    const float* __restrict__ Hin, const float* __restrict__ W,
    const float* __restrict__ bias, float* __restrict__ out)
{
    __shared__ float Hs[64][68];
    __shared__ float Ws3[192];
    __shared__ float bs[3];
    int tid = threadIdx.x, r0 = blockIdx.x*64;
    for (int idx = tid; idx < 64*16; idx += 192) {
        int m2 = idx >> 4, q = idx & 15;
        *(float4*)&Hs[m2][q*4] = *(const float4*)(Hin + (size_t)(r0+m2)*64 + q*4);
    }
    if (tid < 192) Ws3[tid] = W[tid];
    if (tid < 3) bs[tid] = bias[tid];
    __syncthreads();
    int r = tid/3, o = tid%3;
    float acc = bs[o];
#pragma unroll 8
    for (int k = 0; k < 64; k++) acc = fmaf(Hs[r][k], Ws3[o*64+k], acc);
    out[(size_t)(r0+r)*3 + o] = acc;
}

// ---------------- host orchestration ----------------------------------------
extern "C" void kernel_launch(void* const* d_in, const int* in_sizes, int n_in,
                              void* d_out, int out_size) {
    const float* X       = (const float*)d_in[0];
    const float* A       = (const float*)d_in[1];
    const float* Ac      = (const float*)d_in[2];
    const float* embed_w = (const float*)d_in[3];
    const float* embed_b = (const float*)d_in[4];
    const float* topo_eps= (const float*)d_in[5];
    const float* topo_w  = (const float*)d_in[6];
    const float* topo_b  = (const float*)d_in[7];
    const float* theta   = (const float*)d_in[8];
    const float* gin_eps = (const float*)d_in[9];
    const float* gin_w   = (const float*)d_in[10];
    const float* gin_b   = (const float*)d_in[11];
    const float* wo      = (const float*)d_in[12];
    const float* w1      = (const float*)d_in[13];
    const float* wphi    = (const float*)d_in[14];
    const float* wy_w    = (const float*)d_in[15];
    const float* wy_b    = (const float*)d_in[16];
    const float* we_w    = (const float*)d_in[17];
    const float* we_b    = (const float*)d_in[18];
    const float* lin1_w  = (const float*)d_in[19];
    const float* lin1_b  = (const float*)d_in[20];
    const float* lin2_w  = (const float*)d_in[21];
    const float* lin2_b  = (const float*)d_in[22];
    const float* mlp_w   = (const float*)d_in[23];
    const float* mlp_b   = (const float*)d_in[24];
    const float* head1_w = (const float*)d_in[25];
    const float* head1_b = (const float*)d_in[26];
    const float* head2_w = (const float*)d_in[27];
    const float* head2_b = (const float*)d_in[28];
    float* out = (float*)d_out;

    float* S = nullptr;
    cudaGetSymbolAddress((void**)&S, g_scratch);
    const size_t BIG = 524288;
    float* Xh    = S;
    float* Xp    = S + 1*BIG;
    float* aggA  = S + 2*BIG;
    float* aggAc = S + 3*BIG;
    float* XAb   = S + 4*BIG;
    float* XACb  = S + 5*BIG;
    float* Xy    = S + 6*BIG;
    float* bar   = S + 7*BIG;
    float* hob   = S + 8*BIG;
    float* h1b   = hob + 131072;
    float* alphab= h1b + 131072;
    float* y2b   = alphab + 2097152;
    float* h64   = y2b + 1024;

    const int ATTN_SMEM = (16896 + 512 + 32 + 16 + 528 + 512 + 4224 + 128 + 512) * 4; // 93440
    const int GEMM_SMEM = (2*32*68 + 2*32*132) * 4;   // 51200
    cudaFuncSetAttribute(attn_kernel, cudaFuncAttributeMaxDynamicSharedMemorySize, ATTN_SMEM);
    cudaFuncSetAttribute(gemm_multi, cudaFuncAttributeMaxDynamicSharedMemorySize, GEMM_SMEM);

    build_adj<<<dim3(4096, 2), 128>>>(A, Ac);

    {   // embedding
        GJobs js{};
        js.j[0] = GJob{X, embed_w, embed_b, Xh, nullptr, 64, 128, 0};
        gemm_multi<<<dim3(64, 1), 256, GEMM_SMEM>>>(js);
    }
    gin_agg<<<dim3(4096, 2), 128>>>(Xh, aggA, aggAc, topo_eps, topo_eps);
    {
        GJobs js{};
        js.j[0] = GJob{aggA,  topo_w, topo_b, XAb,  nullptr, 128, 128, 1};
        js.j[1] = GJob{aggAc, topo_w, topo_b, XACb, nullptr, 128, 128, 1};
        gemm_multi<<<dim3(64, 2), 256, GEMM_SMEM>>>(js);
    }
    topo_combine<<<2048, 256>>>(Xh, XAb, XACb, theta, Xp);

    for (int l = 0; l < 3; l++) {
        gin_agg<<<dim3(4096, 2), 128>>>(Xp, aggA, aggAc,
                                        gin_eps + l*2, gin_eps + l*2 + 1);
        {
            GJobs js{};
            js.j[0] = GJob{aggA,  gin_w + (size_t)(l*2+0)*16384, gin_b + (l*2+0)*128, XAb,  nullptr, 128, 128, 1};
            js.j[1] = GJob{aggAc, gin_w + (size_t)(l*2+1)*16384, gin_b + (l*2+1)*128, XACb, nullptr, 128, 128, 1};
            js.j[2] = GJob{Xp, wy_w + (size_t)l*16384, wy_b + l*128, Xy, nullptr, 128, 128, 0};
            js.j[3] = GJob{Xp, wo + (size_t)l*4096, nullptr, hob, nullptr, 128, 32, 0};
            js.j[4] = GJob{Xp, w1 + (size_t)l*4096, nullptr, h1b, nullptr, 128, 32, 0};
            gemm_multi<<<dim3(64, 5), 256, GEMM_SMEM>>>(js);
        }
        attn_kernel<<<256, 512, ATTN_SMEM>>>(hob, h1b, wphi + l*32, XAb, XACb,
                                             we_w + (size_t)l*4096, we_b + l*128,
                                             alphab, bar);
        gemm_nn_acc<<<dim3(8, 2, 8), 256>>>(alphab, Xy, bar);
        se_kernel<<<8, 128>>>(bar, lin1_w + (size_t)l*4096, lin1_b + l*32,
                              lin2_w + (size_t)l*4096, lin2_b + l*128, y2b);
        {
            GJobs js{};
            js.j[0] = GJob{bar, mlp_w + (size_t)l*16384, mlp_b + l*128, Xp, y2b, 128, 128, 4};
            gemm_multi<<<dim3(64, 1), 256, GEMM_SMEM>>>(js);
        }
    }
    {
        GJobs js{};
        js.j[0] = GJob{Xp, head1_w, head1_b, h64, nullptr, 128, 64, 1};
        gemm_multi<<<dim3(64, 1), 256, GEMM_SMEM>>>(js);
    }
    head2_kernel<<<64, 192>>>(h64, head2_w, head2_b, out);
}

// round 13
// speedup vs baseline: 1.1608x; 1.0213x over previous
#include <cuda_runtime.h>

__device__ float g_scratch[6816768];
__device__ int g_cnt[2 * 4096];
__device__ int g_adj[2 * 4096 * 96];   // stores j*128 (premultiplied)

__device__ __forceinline__ float tanh_fast(float x) {
    float e = __expf(2.0f * x);
    return 1.0f - __fdividef(2.0f, e + 1.0f);
}
__device__ __forceinline__ float tanh_approx(float x) {
    float y; asm("tanh.approx.f32 %0, %1;" : "=f"(y) : "f"(x)); return y;
}

// ---- packed f32x2 helpers (FFMA2) ------------------------------------------
__device__ __forceinline__ unsigned long long pack2(float x, float y) {
    unsigned long long r;
    asm("mov.b64 %0, {%1, %2};" : "=l"(r) : "f"(x), "f"(y));
    return r;
}
__device__ __forceinline__ unsigned long long ffma2(unsigned long long a,
                                                    unsigned long long b,
                                                    unsigned long long c) {
    unsigned long long d;
    asm("fma.rn.f32x2 %0, %1, %2, %3;" : "=l"(d) : "l"(a), "l"(b), "l"(c));
    return d;
}
__device__ __forceinline__ float2 unpack2(unsigned long long v) {
    float2 f;
    asm("mov.b64 {%0, %1}, %2;" : "=f"(f.x), "=f"(f.y) : "l"(v));
    return f;
}

// ---------------- multi-job thin GEMM (64-row tiles, dbl-buffered, FFMA2) ----
struct GJob { const float* X; const float* W; const float* bias; float* out;
              const float* scale; int K; int NOUT; int flags; };
struct GJobs { GJob j[5]; };

template<int CN>
__device__ __forceinline__ void gemm_inner(unsigned long long accp[4][4],
                                           const float Xs[32][68],
                                           const float Ws[32][132], int tx, int ty) {
#pragma unroll
    for (int k = 0; k < 32; k++) {
        float4 a = *(const float4*)&Xs[k][ty*4];
        unsigned long long pa[4];
        pa[0] = pack2(a.x, a.x); pa[1] = pack2(a.y, a.y);
        pa[2] = pack2(a.z, a.z); pa[3] = pack2(a.w, a.w);
        if (CN == 8) {
            ulonglong2 wA = *(const ulonglong2*)&Ws[k][tx*4];
            ulonglong2 wB = *(const ulonglong2*)&Ws[k][64 + tx*4];
#pragma unroll
            for (int r = 0; r < 4; r++) {
                accp[r][0] = ffma2(pa[r], wA.x, accp[r][0]);
                accp[r][1] = ffma2(pa[r], wA.y, accp[r][1]);
                accp[r][2] = ffma2(pa[r], wB.x, accp[r][2]);
                accp[r][3] = ffma2(pa[r], wB.y, accp[r][3]);
            }
        } else if (CN == 4) {
            ulonglong2 wA = *(const ulonglong2*)&Ws[k][tx*4];
#pragma unroll
            for (int r = 0; r < 4; r++) {
                accp[r][0] = ffma2(pa[r], wA.x, accp[r][0]);
                accp[r][1] = ffma2(pa[r], wA.y, accp[r][1]);
            }
        } else {
            unsigned long long wA = *(const unsigned long long*)&Ws[k][tx*2];
#pragma unroll
            for (int r = 0; r < 4; r++)
                accp[r][0] = ffma2(pa[r], wA, accp[r][0]);
        }
    }
}

__global__ __launch_bounds__(256) void gemm_multi(GJobs jobs) {
    GJob jb = jobs.j[blockIdx.y];
    extern __shared__ float dsm[];
    float (*Xs)[32][68]  = (float(*)[32][68])dsm;
    float (*Ws)[32][132] = (float(*)[32][132])(dsm + 2*32*68);
    int tid = threadIdx.x, tx = tid & 15, ty = tid >> 4;
    int r0 = blockIdx.x * 64;
    unsigned long long accp[4][4];
#pragma unroll
    for (int r = 0; r < 4; r++)
#pragma unroll
        for (int c = 0; c < 4; c++) accp[r][c] = 0ull;
    int cn = jb.NOUT >> 4;
    int bsel = r0 >> 9;
    int nw = jb.NOUT << 3;
    int nk = jb.K >> 5;

    float4 xv[2], wv[4];
    int xm2[2], xq[2];
#pragma unroll
    for (int i = 0; i < 2; i++) { int idx = tid + i*256; xm2[i] = idx >> 3; xq[i] = idx & 7; }

    auto prefetch = [&](int kk) {
#pragma unroll
        for (int i = 0; i < 2; i++) {
            float4 v = *(const float4*)(jb.X + (size_t)(r0 + xm2[i])*jb.K + kk + xq[i]*4);
            if (jb.flags & 4) {
                const float* sc = jb.scale + bsel*128 + kk + xq[i]*4;
                v.x *= sc[0]; v.y *= sc[1]; v.z *= sc[2]; v.w *= sc[3];
            }
            xv[i] = v;
        }
#pragma unroll
        for (int i = 0; i < 4; i++) {
            int idx = tid + i*256;
            if (idx < nw) {
                int n2 = idx >> 3, q = idx & 7;
                wv[i] = *(const float4*)(jb.W + (size_t)n2*jb.K + kk + q*4);
            }
        }
    };
    auto stash = [&](int buf) {
#pragma unroll
        for (int i = 0; i < 2; i++) {
            Xs[buf][xq[i]*4+0][xm2[i]] = xv[i].x;
            Xs[buf][xq[i]*4+1][xm2[i]] = xv[i].y;
            Xs[buf][xq[i]*4+2][xm2[i]] = xv[i].z;
            Xs[buf][xq[i]*4+3][xm2[i]] = xv[i].w;
        }
#pragma unroll
        for (int i = 0; i < 4; i++) {
            int idx = tid + i*256;
            if (idx < nw) {
                int n2 = idx >> 3, q = idx & 7;
                Ws[buf][q*4+0][n2] = wv[i].x;
                Ws[buf][q*4+1][n2] = wv[i].y;
                Ws[buf][q*4+2][n2] = wv[i].z;
                Ws[buf][q*4+3][n2] = wv[i].w;
            }
        }
    };

    prefetch(0);
    stash(0);
    __syncthreads();
    for (int kt = 0; kt < nk; kt++) {
        int buf = kt & 1;
        if (kt + 1 < nk) prefetch((kt + 1) << 5);
        if (cn == 8)      gemm_inner<8>(accp, Xs[buf], Ws[buf], tx, ty);
        else if (cn == 4) gemm_inner<4>(accp, Xs[buf], Ws[buf], tx, ty);
        else              gemm_inner<2>(accp, Xs[buf], Ws[buf], tx, ty);
        if (kt + 1 < nk) {
            stash(buf ^ 1);
            __syncthreads();
        }
    }
#pragma unroll
    for (int r = 0; r < 4; r++) {
        int row = r0 + ty*4 + r;
#pragma unroll
        for (int cp = 0; cp < 4; cp++) {
            if (cp >= (cn >> 1)) break;
            int n2;
            if (cn == 8)      n2 = (cp < 2) ? (tx*4 + cp*2) : (64 + tx*4 + (cp-2)*2);
            else if (cn == 4) n2 = tx*4 + cp*2;
            else              n2 = tx*2;
            float2 v = unpack2(accp[r][cp]);
            if (jb.bias) { v.x += jb.bias[n2]; v.y += jb.bias[n2+1]; }
            if (jb.flags & 1) { v.x = fmaxf(v.x, 0.f); v.y = fmaxf(v.y, 0.f); }
            jb.out[(size_t)row*jb.NOUT + n2]     = v.x;
            jb.out[(size_t)row*jb.NOUT + n2 + 1] = v.y;
        }
    }
}

// ---------------- adjacency precompute ---------------------------------------
__global__ __launch_bounds__(128) void build_adj(
    const float* __restrict__ A, const float* __restrict__ Ac)
{
    __shared__ int lst[512];
    __shared__ int cnt;
    int bi = blockIdx.x, g = blockIdx.y;
    const float* M = (g == 0) ? A : Ac;
    int tid = threadIdx.x;
    if (tid == 0) cnt = 0;
    __syncthreads();
    float4 v = *(const float4*)(M + (size_t)bi*512 + tid*4);
    if (v.x != 0.f) lst[atomicAdd(&cnt,1)] = (tid*4+0)*128;
    if (v.y != 0.f) lst[atomicAdd(&cnt,1)] = (tid*4+1)*128;
    if (v.z != 0.f) lst[atomicAdd(&cnt,1)] = (tid*4+2)*128;
    if (v.w != 0.f) lst[atomicAdd(&cnt,1)] = (tid*4+3)*128;
    __syncthreads();
    int n = min(cnt, 96);
    if (tid == 0) g_cnt[g*4096 + bi] = n;
    for (int k = tid; k < n; k += 128) g_adj[(size_t)(g*4096 + bi)*96 + k] = lst[k];
}

// ---------------- sparse GIN aggregation v3: 32 lanes/node, float4 gather ----
// grid (1024, 2), block 128 = 4 nodes x 32 lanes; warps independent.
__global__ __launch_bounds__(128) void gin_agg(
    const float* __restrict__ X, float* __restrict__ outA, float* __restrict__ outAc,
    const float* __restrict__ epsA, const float* __restrict__ epsAc)
{
    __shared__ int lst[4][96];
    int g = blockIdx.y;
    float* out = (g == 0) ? outA : outAc;
    const float* ep = (g == 0) ? epsA : epsAc;
    int tid = threadIdx.x;
    int local = tid >> 5, lane = tid & 31;
    int bi = blockIdx.x * 4 + local;
    int n = g_cnt[g*4096 + bi];
    for (int k = lane; k < n; k += 32)
        lst[local][k] = g_adj[(size_t)(g*4096 + bi)*96 + k];
    __syncwarp();
    int b = bi >> 9;
    float eps1 = 1.0f + *ep;
    float4 acc = *(const float4*)(X + (size_t)bi*128 + lane*4);
    acc.x *= eps1; acc.y *= eps1; acc.z *= eps1; acc.w *= eps1;
    const float* Xb = X + (size_t)(b << 9)*128 + lane*4;
    const int* ls = lst[local];
    int k = 0;
    for (; k + 4 <= n; k += 4) {
        float4 v0 = *(const float4*)(Xb + ls[k]);
        float4 v1 = *(const float4*)(Xb + ls[k+1]);
        float4 v2 = *(const float4*)(Xb + ls[k+2]);
        float4 v3 = *(const float4*)(Xb + ls[k+3]);
        acc.x += (v0.x + v1.x) + (v2.x + v3.x);
        acc.y += (v0.y + v1.y) + (v2.y + v3.y);
        acc.z += (v0.z + v1.z) + (v2.z + v3.z);
        acc.w += (v0.w + v1.w) + (v2.w + v3.w);
    }
    for (; k < n; k++) {
        float4 v = *(const float4*)(Xb + ls[k]);
        acc.x += v.x; acc.y += v.y; acc.z += v.z; acc.w += v.w;
    }
    *(float4*)(out + (size_t)bi*128 + lane*4) = acc;
}

// ---------------- topo combine ----------------------------------------------
__global__ void topo_combine(const float* __restrict__ Xh, const float* __restrict__ hA,
                             const float* __restrict__ hAC, const float* __restrict__ theta,
                             float* __restrict__ Xp)
{
    int idx = blockIdx.x*256 + threadIdx.x;
    int h = idx & 127;
    Xp[idx] = Xh[idx] + tanh_fast(hA[idx]*theta[2*h]) + tanh_fast(hAC[idx]*theta[2*h+1]);
}

// ---------------- fused flexible attention v5 (stride-34, float2 t-stores) ---
__global__ __launch_bounds__(512) void attn_kernel(
    const float* __restrict__ ho, const float* __restrict__ h1,
    const float* __restrict__ wphi,
    const float* __restrict__ XA, const float* __restrict__ XAC,
    const float* __restrict__ wew, const float* __restrict__ web,
    float* __restrict__ alpha, float* __restrict__ bar)
{
    extern __shared__ float sm[];
    float* work  = sm;                // 512*34 = 17408 (raw tanh values)
    float* hos   = sm + 17408;        // 512
    float* wps   = hos + 512;         // 32
    float* part  = wps + 32;          // 16
    float* cpart = part + 16;         // 16*33 = 528
    float* ctxa  = cpart + 528;       // 16*32 = 512
    float* wews  = ctxa + 512;        // 128*33 = 4224
    float* webs  = wews + 4224;       // 128
    float* ss    = webs + 128;        // 512 (raw exp values)

    int tid = threadIdx.x;
    int lane = tid & 31, w = tid >> 5;
    int b = blockIdx.x >> 5;
    int i0 = (blockIdx.x & 31) << 4;

    float h1r[32];
    {
        const float4* src = (const float4*)(h1 + ((size_t)b*512 + tid)*32);
#pragma unroll
        for (int q = 0; q < 8; q++) {
            float4 v = src[q];
            h1r[q*4+0]=v.x; h1r[q*4+1]=v.y; h1r[q*4+2]=v.z; h1r[q*4+3]=v.w;
        }
    }
    hos[tid] = ho[((size_t)b*512 + i0)*32 + tid];
    if (tid < 32) wps[tid] = wphi[tid];
    if (tid < 128) webs[tid] = web[tid];
#pragma unroll
    for (int idx = tid; idx < 4096; idx += 512) {
        int hh = idx >> 5, d = idx & 31;
        wews[hh*33 + d] = wew[idx];
    }
    __syncthreads();

    for (int ii = 0; ii < 16; ii++) {
        float t[32];
        float s = 0.f;
        const float* hoi = hos + ii*32;
#pragma unroll
        for (int d = 0; d < 32; d++) {
            t[d] = tanh_approx(hoi[d] + h1r[d]);
            s = fmaf(wps[d], t[d], s);
        }
        float e = __expf(s);
        float es = e;
#pragma unroll
        for (int o = 16; o; o >>= 1) es += __shfl_xor_sync(0xffffffffu, es, o);
        if (lane == 0) part[w] = es;
        ss[tid] = e;
        float2* wr2 = (float2*)(work + tid*34);
#pragma unroll
        for (int d = 0; d < 16; d++) wr2[d] = make_float2(t[2*d], t[2*d+1]);
        __syncthreads();
        float tot = part[0];
#pragma unroll
        for (int q = 1; q < 16; q++) tot += part[q];
        float inv = 1.0f / tot;
        alpha[((size_t)(b*512 + i0 + ii))*512 + tid] = e * inv;
        {
            float acc = 0.f;
            const float* base = work + (w*32)*34 + lane;
            const float* eb = ss + w*32;
#pragma unroll
            for (int k = 0; k < 32; k++) acc = fmaf(eb[k], base[k*34], acc);
            cpart[w*33 + lane] = acc;
        }
        __syncthreads();
        if (tid < 32) {
            float c = 0.f;
#pragma unroll
            for (int q = 0; q < 16; q++) c += cpart[q*33 + tid];
            ctxa[ii*32 + tid] = c * inv;
        }
    }
    __syncthreads();

#pragma unroll
    for (int r = 0; r < 4; r++) {
        int o = tid + r*512;
        int ii = o >> 7, hh = o & 127;
        size_t row = (size_t)b*512 + i0 + ii;
        float v = XA[row*128 + hh] + XAC[row*128 + hh] + webs[hh];
        const float* cw = wews + hh*33;
        const float* cx = ctxa + ii*32;
#pragma unroll
        for (int d = 0; d < 32; d++) v = fmaf(cx[d], cw[d], v);
        bar[row*128 + hh] = v;
    }
}

// ---------------- batched NN GEMM accumulate (FFMA2 inner) --------------------
__global__ __launch_bounds__(256) void gemm_nn_acc(
    const float* __restrict__ al, const float* __restrict__ Bx, float* __restrict__ C)
{
    __shared__ float As[2][32][68];
    __shared__ float Bs[2][32][68];
    int b = blockIdx.z, m0 = blockIdx.x*64, n0 = blockIdx.y*64;
    int tid = threadIdx.x, tx = tid & 15, ty = tid >> 4;
    const float* Ab = al + (size_t)b*512*512;
    const float* Bb = Bx + (size_t)b*512*128;
    unsigned long long accp[4][2];
#pragma unroll
    for (int r = 0; r < 4; r++) { accp[r][0] = 0ull; accp[r][1] = 0ull; }

    float4 av[2], bv[2];
    auto prefetch = [&](int k0) {
#pragma unroll
        for (int i = 0; i < 2; i++) {
            int idx = tid + i*256;
            int mm = idx >> 3, q = idx & 7;
            av[i] = *(const float4*)(Ab + (size_t)(m0+mm)*512 + k0 + q*4);
        }
#pragma unroll
        for (int i = 0; i < 2; i++) {
            int idx = tid + i*256;
            int kk = idx >> 4, q = idx & 15;
            bv[i] = *(const float4*)(Bb + (size_t)(k0+kk)*128 + n0 + q*4);
        }
    };
    auto stash = [&](int buf) {
#pragma unroll
        for (int i = 0; i < 2; i++) {
            int idx = tid + i*256;
            int mm = idx >> 3, q = idx & 7;
            As[buf][q*4+0][mm]=av[i].x; As[buf][q*4+1][mm]=av[i].y;
            As[buf][q*4+2][mm]=av[i].z; As[buf][q*4+3][mm]=av[i].w;
        }
#pragma unroll
        for (int i = 0; i < 2; i++) {
            int idx = tid + i*256;
            int kk = idx >> 4, q = idx & 15;
            *(float4*)&Bs[buf][kk][q*4] = bv[i];
        }
    };

    prefetch(0);
    stash(0);
    __syncthreads();
    for (int kt = 0; kt < 16; kt++) {
        int buf = kt & 1;
        if (kt + 1 < 16) prefetch((kt + 1) << 5);
#pragma unroll
        for (int k = 0; k < 32; k++) {
            float4 a = *(const float4*)&As[buf][k][ty*4];
            ulonglong2 wb = *(const ulonglong2*)&Bs[buf][k][tx*4];
            unsigned long long pa[4];
            pa[0] = pack2(a.x, a.x); pa[1] = pack2(a.y, a.y);
            pa[2] = pack2(a.z, a.z); pa[3] = pack2(a.w, a.w);
#pragma unroll
            for (int r = 0; r < 4; r++) {
                accp[r][0] = ffma2(pa[r], wb.x, accp[r][0]);
                accp[r][1] = ffma2(pa[r], wb.y, accp[r][1]);
            }
        }
        if (kt + 1 < 16) {
            stash(buf ^ 1);
            __syncthreads();
        }
    }
    float* Cb = C + (size_t)b*512*128;
#pragma unroll
    for (int r = 0; r < 4; r++)
#pragma unroll
        for (int cp = 0; cp < 2; cp++) {
            float2 v = unpack2(accp[r][cp]);
            size_t base = (size_t)(m0+ty*4+r)*128 + n0 + tx*4 + cp*2;
            Cb[base]     += v.x;
            Cb[base + 1] += v.y;
        }
}

// ---------------- SE block ---------------------------------------------------
__global__ __launch_bounds__(128) void se_kernel(
    const float* __restrict__ bar, const float* __restrict__ w1,
    const float* __restrict__ b1, const float* __restrict__ w2,
    const float* __restrict__ b2, float* __restrict__ y2)
{
    __shared__ float pooled[128];
    __shared__ float y1s[32];
    int b = blockIdx.x, tid = threadIdx.x;
    const float* base = bar + (size_t)(b << 9)*128 + tid;
    float p = 0.f;
#pragma unroll 8
    for (int n = 0; n < 512; n++) p += base[n*128];
    pooled[tid] = p;
    __syncthreads();
    if (tid < 32) {
        float v = b1[tid];
        const float* wr = w1 + tid*128;
#pragma unroll 8
        for (int h = 0; h < 128; h++) v = fmaf(pooled[h], wr[h], v);
        y1s[tid] = fmaxf(v, 0.f);
    }
    __syncthreads();
    float v = b2[tid];
    const float* wr = w2 + tid*32;
#pragma unroll
    for (int r = 0; r < 32; r++) v = fmaf(y1s[r], wr[r], v);
    y2[b*128 + tid] = __fdividef(1.0f, 1.0f + __expf(-v));
}

// ---------------- head2: out[4096,3] -----------------------------------------
__global__ __launch_bounds__(192) void head2_kernel(
    const float* __restrict__ Hin, const float* __restrict__ W,
    const float* __restrict__ bias, float* __restrict__ out)
{
    __shared__ float Hs[64][68];
    __shared__ float Ws3[192];
    __shared__ float bs[3];
    int tid = threadIdx.x, r0 = blockIdx.x*64;
    for (int idx = tid; idx < 64*16; idx += 192) {
        int m2 = idx >> 4, q = idx & 15;
        *(float4*)&Hs[m2][q*4] = *(const float4*)(Hin + (size_t)(r0+m2)*64 + q*4);
    }
    if (tid < 192) Ws3[tid] = W[tid];
    if (tid < 3) bs[tid] = bias[tid];
    __syncthreads();
    int r = tid/3, o = tid%3;
    float acc = bs[o];
#pragma unroll 8
    for (int k = 0; k < 64; k++) acc = fmaf(Hs[r][k], Ws3[o*64+k], acc);
    out[(size_t)(r0+r)*3 + o] = acc;
}

// ---------------- host orchestration ----------------------------------------
extern "C" void kernel_launch(void* const* d_in, const int* in_sizes, int n_in,
                              void* d_out, int out_size) {
    const float* X       = (const float*)d_in[0];
    const float* A       = (const float*)d_in[1];
    const float* Ac      = (const float*)d_in[2];
    const float* embed_w = (const float*)d_in[3];
    const float* embed_b = (const float*)d_in[4];
    const float* topo_eps= (const float*)d_in[5];
    const float* topo_w  = (const float*)d_in[6];
    const float* topo_b  = (const float*)d_in[7];
    const float* theta   = (const float*)d_in[8];
    const float* gin_eps = (const float*)d_in[9];
    const float* gin_w   = (const float*)d_in[10];
    const float* gin_b   = (const float*)d_in[11];
    const float* wo      = (const float*)d_in[12];
    const float* w1      = (const float*)d_in[13];
    const float* wphi    = (const float*)d_in[14];
    const float* wy_w    = (const float*)d_in[15];
    const float* wy_b    = (const float*)d_in[16];
    const float* we_w    = (const float*)d_in[17];
    const float* we_b    = (const float*)d_in[18];
    const float* lin1_w  = (const float*)d_in[19];
    const float* lin1_b  = (const float*)d_in[20];
    const float* lin2_w  = (const float*)d_in[21];
    const float* lin2_b  = (const float*)d_in[22];
    const float* mlp_w   = (const float*)d_in[23];
    const float* mlp_b   = (const float*)d_in[24];
    const float* head1_w = (const float*)d_in[25];
    const float* head1_b = (const float*)d_in[26];
    const float* head2_w = (const float*)d_in[27];
    const float* head2_b = (const float*)d_in[28];
    float* out = (float*)d_out;

    float* S = nullptr;
    cudaGetSymbolAddress((void**)&S, g_scratch);
    const size_t BIG = 524288;
    float* Xh    = S;
    float* Xp    = S + 1*BIG;
    float* aggA  = S + 2*BIG;
    float* aggAc = S + 3*BIG;
    float* XAb   = S + 4*BIG;
    float* XACb  = S + 5*BIG;
    float* Xy    = S + 6*BIG;
    float* bar   = S + 7*BIG;
    float* hob   = S + 8*BIG;
    float* h1b   = hob + 131072;
    float* alphab= h1b + 131072;
    float* y2b   = alphab + 2097152;
    float* h64   = y2b + 1024;

    const int ATTN_SMEM = (17408 + 512 + 32 + 16 + 528 + 512 + 4224 + 128 + 512) * 4; // 95488
    const int GEMM_SMEM = (2*32*68 + 2*32*132) * 4;   // 51200
    cudaFuncSetAttribute(attn_kernel, cudaFuncAttributeMaxDynamicSharedMemorySize, ATTN_SMEM);
    cudaFuncSetAttribute(gemm_multi, cudaFuncAttributeMaxDynamicSharedMemorySize, GEMM_SMEM);

    build_adj<<<dim3(4096, 2), 128>>>(A, Ac);

    {   // embedding
        GJobs js{};
        js.j[0] = GJob{X, embed_w, embed_b, Xh, nullptr, 64, 128, 0};
        gemm_multi<<<dim3(64, 1), 256, GEMM_SMEM>>>(js);
    }
    gin_agg<<<dim3(1024, 2), 128>>>(Xh, aggA, aggAc, topo_eps, topo_eps);
    {
        GJobs js{};
        js.j[0] = GJob{aggA,  topo_w, topo_b, XAb,  nullptr, 128, 128, 1};
        js.j[1] = GJob{aggAc, topo_w, topo_b, XACb, nullptr, 128, 128, 1};
        gemm_multi<<<dim3(64, 2), 256, GEMM_SMEM>>>(js);
    }
    topo_combine<<<2048, 256>>>(Xh, XAb, XACb, theta, Xp);

    for (int l = 0; l < 3; l++) {
        gin_agg<<<dim3(1024, 2), 128>>>(Xp, aggA, aggAc,
                                        gin_eps + l*2, gin_eps + l*2 + 1);
        {
            GJobs js{};
            js.j[0] = GJob{aggA,  gin_w + (size_t)(l*2+0)*16384, gin_b + (l*2+0)*128, XAb,  nullptr, 128, 128, 1};
            js.j[1] = GJob{aggAc, gin_w + (size_t)(l*2+1)*16384, gin_b + (l*2+1)*128, XACb, nullptr, 128, 128, 1};
            js.j[2] = GJob{Xp, wy_w + (size_t)l*16384, wy_b + l*128, Xy, nullptr, 128, 128, 0};
            js.j[3] = GJob{Xp, wo + (size_t)l*4096, nullptr, hob, nullptr, 128, 32, 0};
            js.j[4] = GJob{Xp, w1 + (size_t)l*4096, nullptr, h1b, nullptr, 128, 32, 0};
            gemm_multi<<<dim3(64, 5), 256, GEMM_SMEM>>>(js);
        }
        attn_kernel<<<256, 512, ATTN_SMEM>>>(hob, h1b, wphi + l*32, XAb, XACb,
                                             we_w + (size_t)l*4096, we_b + l*128,
                                             alphab, bar);
        gemm_nn_acc<<<dim3(8, 2, 8), 256>>>(alphab, Xy, bar);
        se_kernel<<<8, 128>>>(bar, lin1_w + (size_t)l*4096, lin1_b + l*32,
                              lin2_w + (size_t)l*4096, lin2_b + l*128, y2b);
        {
            GJobs js{};
            js.j[0] = GJob{bar, mlp_w + (size_t)l*16384, mlp_b + l*128, Xp, y2b, 128, 128, 4};
            gemm_multi<<<dim3(64, 1), 256, GEMM_SMEM>>>(js);
        }
    }
    {
        GJobs js{};
        js.j[0] = GJob{Xp, head1_w, head1_b, h64, nullptr, 128, 64, 1};
        gemm_multi<<<dim3(64, 1), 256, GEMM_SMEM>>>(js);
    }
    head2_kernel<<<64, 192>>>(h64, head2_w, head2_b, out);
}

// round 14
// speedup vs baseline: 1.1820x; 1.0182x over previous
#include <cuda_runtime.h>

__device__ float g_scratch[6816768];
__device__ int g_cnt[2 * 4096];
__device__ int g_adj[2 * 4096 * 96];   // stores j*128 (premultiplied)

__device__ __forceinline__ float tanh_fast(float x) {
    float e = __expf(2.0f * x);
    return 1.0f - __fdividef(2.0f, e + 1.0f);
}
__device__ __forceinline__ float tanh_approx(float x) {
    float y; asm("tanh.approx.f32 %0, %1;" : "=f"(y) : "f"(x)); return y;
}

// ---- packed f32x2 helpers (FFMA2) ------------------------------------------
__device__ __forceinline__ unsigned long long pack2(float x, float y) {
    unsigned long long r;
    asm("mov.b64 %0, {%1, %2};" : "=l"(r) : "f"(x), "f"(y));
    return r;
}
__device__ __forceinline__ unsigned long long ffma2(unsigned long long a,
                                                    unsigned long long b,
                                                    unsigned long long c) {
    unsigned long long d;
    asm("fma.rn.f32x2 %0, %1, %2, %3;" : "=l"(d) : "l"(a), "l"(b), "l"(c));
    return d;
}
__device__ __forceinline__ float2 unpack2(unsigned long long v) {
    float2 f;
    asm("mov.b64 {%0, %1}, %2;" : "=f"(f.x), "=f"(f.y) : "l"(v));
    return f;
}

struct GJob { const float* X; const float* W; const float* bias; float* out;
              const float* scale; int K; int NOUT; int flags; };
struct GJobs { GJob j[5]; };

// ---------------- multi-job thin GEMM (64-row tiles, dbl-buffered, FFMA2) ----
template<int CN>
__device__ __forceinline__ void gemm_inner(unsigned long long accp[4][4],
                                           const float Xs[32][68],
                                           const float Ws[32][132], int tx, int ty) {
#pragma unroll
    for (int k = 0; k < 32; k++) {
        float4 a = *(const float4*)&Xs[k][ty*4];
        unsigned long long pa[4];
        pa[0] = pack2(a.x, a.x); pa[1] = pack2(a.y, a.y);
        pa[2] = pack2(a.z, a.z); pa[3] = pack2(a.w, a.w);
        if (CN == 8) {
            ulonglong2 wA = *(const ulonglong2*)&Ws[k][tx*4];
            ulonglong2 wB = *(const ulonglong2*)&Ws[k][64 + tx*4];
#pragma unroll
            for (int r = 0; r < 4; r++) {
                accp[r][0] = ffma2(pa[r], wA.x, accp[r][0]);
                accp[r][1] = ffma2(pa[r], wA.y, accp[r][1]);
                accp[r][2] = ffma2(pa[r], wB.x, accp[r][2]);
                accp[r][3] = ffma2(pa[r], wB.y, accp[r][3]);
            }
        } else if (CN == 4) {
            ulonglong2 wA = *(const ulonglong2*)&Ws[k][tx*4];
#pragma unroll
            for (int r = 0; r < 4; r++) {
                accp[r][0] = ffma2(pa[r], wA.x, accp[r][0]);
                accp[r][1] = ffma2(pa[r], wA.y, accp[r][1]);
            }
        } else {
            unsigned long long wA = *(const unsigned long long*)&Ws[k][tx*2];
#pragma unroll
            for (int r = 0; r < 4; r++)
                accp[r][0] = ffma2(pa[r], wA, accp[r][0]);
        }
    }
}

__global__ __launch_bounds__(256) void gemm_multi(GJobs jobs) {
    GJob jb = jobs.j[blockIdx.y];
    extern __shared__ float dsm[];
    float (*Xs)[32][68]  = (float(*)[32][68])dsm;
    float (*Ws)[32][132] = (float(*)[32][132])(dsm + 2*32*68);
    int tid = threadIdx.x, tx = tid & 15, ty = tid >> 4;
    int r0 = blockIdx.x * 64;
    unsigned long long accp[4][4];
#pragma unroll
    for (int r = 0; r < 4; r++)
#pragma unroll
        for (int c = 0; c < 4; c++) accp[r][c] = 0ull;
    int cn = jb.NOUT >> 4;
    int bsel = r0 >> 9;
    int nw = jb.NOUT << 3;
    int nk = jb.K >> 5;

    float4 xv[2], wv[4];
    int xm2[2], xq[2];
#pragma unroll
    for (int i = 0; i < 2; i++) { int idx = tid + i*256; xm2[i] = idx >> 3; xq[i] = idx & 7; }

    auto prefetch = [&](int kk) {
#pragma unroll
        for (int i = 0; i < 2; i++) {
            float4 v = *(const float4*)(jb.X + (size_t)(r0 + xm2[i])*jb.K + kk + xq[i]*4);
            if (jb.flags & 4) {
                const float* sc = jb.scale + bsel*128 + kk + xq[i]*4;
                v.x *= sc[0]; v.y *= sc[1]; v.z *= sc[2]; v.w *= sc[3];
            }
            xv[i] = v;
        }
#pragma unroll
        for (int i = 0; i < 4; i++) {
            int idx = tid + i*256;
            if (idx < nw) {
                int n2 = idx >> 3, q = idx & 7;
                wv[i] = *(const float4*)(jb.W + (size_t)n2*jb.K + kk + q*4);
            }
        }
    };
    auto stash = [&](int buf) {
#pragma unroll
        for (int i = 0; i < 2; i++) {
            Xs[buf][xq[i]*4+0][xm2[i]] = xv[i].x;
            Xs[buf][xq[i]*4+1][xm2[i]] = xv[i].y;
            Xs[buf][xq[i]*4+2][xm2[i]] = xv[i].z;
            Xs[buf][xq[i]*4+3][xm2[i]] = xv[i].w;
        }
#pragma unroll
        for (int i = 0; i < 4; i++) {
            int idx = tid + i*256;
            if (idx < nw) {
                int n2 = idx >> 3, q = idx & 7;
                Ws[buf][q*4+0][n2] = wv[i].x;
                Ws[buf][q*4+1][n2] = wv[i].y;
                Ws[buf][q*4+2][n2] = wv[i].z;
                Ws[buf][q*4+3][n2] = wv[i].w;
            }
        }
    };

    prefetch(0);
    stash(0);
    __syncthreads();
    for (int kt = 0; kt < nk; kt++) {
        int buf = kt & 1;
        if (kt + 1 < nk) prefetch((kt + 1) << 5);
        if (cn == 8)      gemm_inner<8>(accp, Xs[buf], Ws[buf], tx, ty);
        else if (cn == 4) gemm_inner<4>(accp, Xs[buf], Ws[buf], tx, ty);
        else              gemm_inner<2>(accp, Xs[buf], Ws[buf], tx, ty);
        if (kt + 1 < nk) {
            stash(buf ^ 1);
            __syncthreads();
        }
    }
#pragma unroll
    for (int r = 0; r < 4; r++) {
        int row = r0 + ty*4 + r;
#pragma unroll
        for (int cp = 0; cp < 4; cp++) {
            if (cp >= (cn >> 1)) break;
            int n2;
            if (cn == 8)      n2 = (cp < 2) ? (tx*4 + cp*2) : (64 + tx*4 + (cp-2)*2);
            else if (cn == 4) n2 = tx*4 + cp*2;
            else              n2 = tx*2;
            float2 v = unpack2(accp[r][cp]);
            if (jb.bias) { v.x += jb.bias[n2]; v.y += jb.bias[n2+1]; }
            if (jb.flags & 1) { v.x = fmaxf(v.x, 0.f); v.y = fmaxf(v.y, 0.f); }
            jb.out[(size_t)row*jb.NOUT + n2]     = v.x;
            jb.out[(size_t)row*jb.NOUT + n2 + 1] = v.y;
        }
    }
}

// ---------------- single-job GEMM, 32-row tiles (128 blocks -> more SMs) -----
template<int CN>
__device__ __forceinline__ void gemm_inner_h(unsigned long long accp[2][4],
                                             const float Xs[32][36],
                                             const float Ws[32][132], int tx, int ty) {
#pragma unroll
    for (int k = 0; k < 32; k++) {
        float2 a = *(const float2*)&Xs[k][ty*2];
        unsigned long long pa0 = pack2(a.x, a.x);
        unsigned long long pa1 = pack2(a.y, a.y);
        if (CN == 8) {
            ulonglong2 wA = *(const ulonglong2*)&Ws[k][tx*4];
            ulonglong2 wB = *(const ulonglong2*)&Ws[k][64 + tx*4];
            accp[0][0] = ffma2(pa0, wA.x, accp[0][0]);
            accp[0][1] = ffma2(pa0, wA.y, accp[0][1]);
            accp[0][2] = ffma2(pa0, wB.x, accp[0][2]);
            accp[0][3] = ffma2(pa0, wB.y, accp[0][3]);
            accp[1][0] = ffma2(pa1, wA.x, accp[1][0]);
            accp[1][1] = ffma2(pa1, wA.y, accp[1][1]);
            accp[1][2] = ffma2(pa1, wB.x, accp[1][2]);
            accp[1][3] = ffma2(pa1, wB.y, accp[1][3]);
        } else { // CN == 4
            ulonglong2 wA = *(const ulonglong2*)&Ws[k][tx*4];
            accp[0][0] = ffma2(pa0, wA.x, accp[0][0]);
            accp[0][1] = ffma2(pa0, wA.y, accp[0][1]);
            accp[1][0] = ffma2(pa1, wA.x, accp[1][0]);
            accp[1][1] = ffma2(pa1, wA.y, accp[1][1]);
        }
    }
}

__global__ __launch_bounds__(256) void gemm_half(GJob jb) {
    extern __shared__ float dsm[];
    float (*Xs)[32][36]  = (float(*)[32][36])dsm;                 // 2*1152
    float (*Ws)[32][132] = (float(*)[32][132])(dsm + 2*32*36);    // 2*4224
    int tid = threadIdx.x, tx = tid & 15, ty = tid >> 4;
    int r0 = blockIdx.x * 32;
    unsigned long long accp[2][4];
#pragma unroll
    for (int r = 0; r < 2; r++)
#pragma unroll
        for (int c = 0; c < 4; c++) accp[r][c] = 0ull;
    int cn = jb.NOUT >> 4;
    int bsel = r0 >> 9;
    int nw = jb.NOUT << 3;
    int nk = jb.K >> 5;
    int xm = tid >> 3, xq = tid & 7;

    float4 xv, wv[4];
    auto prefetch = [&](int kk) {
        float4 v = *(const float4*)(jb.X + (size_t)(r0 + xm)*jb.K + kk + xq*4);
        if (jb.flags & 4) {
            const float* sc = jb.scale + bsel*128 + kk + xq*4;
            v.x *= sc[0]; v.y *= sc[1]; v.z *= sc[2]; v.w *= sc[3];
        }
        xv = v;
#pragma unroll
        for (int i = 0; i < 4; i++) {
            int idx = tid + i*256;
            if (idx < nw) {
                int n2 = idx >> 3, q = idx & 7;
                wv[i] = *(const float4*)(jb.W + (size_t)n2*jb.K + kk + q*4);
            }
        }
    };
    auto stash = [&](int buf) {
        Xs[buf][xq*4+0][xm] = xv.x;
        Xs[buf][xq*4+1][xm] = xv.y;
        Xs[buf][xq*4+2][xm] = xv.z;
        Xs[buf][xq*4+3][xm] = xv.w;
#pragma unroll
        for (int i = 0; i < 4; i++) {
            int idx = tid + i*256;
            if (idx < nw) {
                int n2 = idx >> 3, q = idx & 7;
                Ws[buf][q*4+0][n2] = wv[i].x;
                Ws[buf][q*4+1][n2] = wv[i].y;
                Ws[buf][q*4+2][n2] = wv[i].z;
                Ws[buf][q*4+3][n2] = wv[i].w;
            }
        }
    };

    prefetch(0);
    stash(0);
    __syncthreads();
    for (int kt = 0; kt < nk; kt++) {
        int buf = kt & 1;
        if (kt + 1 < nk) prefetch((kt + 1) << 5);
        if (cn == 8) gemm_inner_h<8>(accp, Xs[buf], Ws[buf], tx, ty);
        else         gemm_inner_h<4>(accp, Xs[buf], Ws[buf], tx, ty);
        if (kt + 1 < nk) {
            stash(buf ^ 1);
            __syncthreads();
        }
    }
#pragma unroll
    for (int r = 0; r < 2; r++) {
        int row = r0 + ty*2 + r;
#pragma unroll
        for (int cp = 0; cp < 4; cp++) {
            if (cp >= (cn >> 1)) break;
            int n2;
            if (cn == 8) n2 = (cp < 2) ? (tx*4 + cp*2) : (64 + tx*4 + (cp-2)*2);
            else         n2 = tx*4 + cp*2;
            float2 v = unpack2(accp[r][cp]);
            if (jb.bias) { v.x += jb.bias[n2]; v.y += jb.bias[n2+1]; }
            if (jb.flags & 1) { v.x = fmaxf(v.x, 0.f); v.y = fmaxf(v.y, 0.f); }
            jb.out[(size_t)row*jb.NOUT + n2]     = v.x;
            jb.out[(size_t)row*jb.NOUT + n2 + 1] = v.y;
        }
    }
}

// ---------------- adjacency precompute ---------------------------------------
__global__ __launch_bounds__(128) void build_adj(
    const float* __restrict__ A, const float* __restrict__ Ac)
{
    __shared__ int lst[512];
    __shared__ int cnt;
    int bi = blockIdx.x, g = blockIdx.y;
    const float* M = (g == 0) ? A : Ac;
    int tid = threadIdx.x;
    if (tid == 0) cnt = 0;
    __syncthreads();
    float4 v = *(const float4*)(M + (size_t)bi*512 + tid*4);
    if (v.x != 0.f) lst[atomicAdd(&cnt,1)] = (tid*4+0)*128;
    if (v.y != 0.f) lst[atomicAdd(&cnt,1)] = (tid*4+1)*128;
    if (v.z != 0.f) lst[atomicAdd(&cnt,1)] = (tid*4+2)*128;
    if (v.w != 0.f) lst[atomicAdd(&cnt,1)] = (tid*4+3)*128;
    __syncthreads();
    int n = min(cnt, 96);
    if (tid == 0) g_cnt[g*4096 + bi] = n;
    for (int k = tid; k < n; k += 128) g_adj[(size_t)(g*4096 + bi)*96 + k] = lst[k];
}

// ---------------- sparse GIN aggregation v3 ----------------------------------
__global__ __launch_bounds__(128) void gin_agg(
    const float* __restrict__ X, float* __restrict__ outA, float* __restrict__ outAc,
    const float* __restrict__ epsA, const float* __restrict__ epsAc)
{
    __shared__ int lst[4][96];
    int g = blockIdx.y;
    float* out = (g == 0) ? outA : outAc;
    const float* ep = (g == 0) ? epsA : epsAc;
    int tid = threadIdx.x;
    int local = tid >> 5, lane = tid & 31;
    int bi = blockIdx.x * 4 + local;
    int n = g_cnt[g*4096 + bi];
    for (int k = lane; k < n; k += 32)
        lst[local][k] = g_adj[(size_t)(g*4096 + bi)*96 + k];
    __syncwarp();
    int b = bi >> 9;
    float eps1 = 1.0f + *ep;
    float4 acc = *(const float4*)(X + (size_t)bi*128 + lane*4);
    acc.x *= eps1; acc.y *= eps1; acc.z *= eps1; acc.w *= eps1;
    const float* Xb = X + (size_t)(b << 9)*128 + lane*4;
    const int* ls = lst[local];
    int k = 0;
    for (; k + 4 <= n; k += 4) {
        float4 v0 = *(const float4*)(Xb + ls[k]);
        float4 v1 = *(const float4*)(Xb + ls[k+1]);
        float4 v2 = *(const float4*)(Xb + ls[k+2]);
        float4 v3 = *(const float4*)(Xb + ls[k+3]);
        acc.x += (v0.x + v1.x) + (v2.x + v3.x);
        acc.y += (v0.y + v1.y) + (v2.y + v3.y);
        acc.z += (v0.z + v1.z) + (v2.z + v3.z);
        acc.w += (v0.w + v1.w) + (v2.w + v3.w);
    }
    for (; k < n; k++) {
        float4 v = *(const float4*)(Xb + ls[k]);
        acc.x += v.x; acc.y += v.y; acc.z += v.z; acc.w += v.w;
    }
    *(float4*)(out + (size_t)bi*128 + lane*4) = acc;
}

// ---------------- topo combine ----------------------------------------------
__global__ void topo_combine(const float* __restrict__ Xh, const float* __restrict__ hA,
                             const float* __restrict__ hAC, const float* __restrict__ theta,
                             float* __restrict__ Xp)
{
    int idx = blockIdx.x*256 + threadIdx.x;
    int h = idx & 127;
    Xp[idx] = Xh[idx] + tanh_fast(hA[idx]*theta[2*h]) + tanh_fast(hAC[idx]*theta[2*h+1]);
}

// ---------------- fused flexible attention v5 ---------------------------------
__global__ __launch_bounds__(512) void attn_kernel(
    const float* __restrict__ ho, const float* __restrict__ h1,
    const float* __restrict__ wphi,
    const float* __restrict__ XA, const float* __restrict__ XAC,
    const float* __restrict__ wew, const float* __restrict__ web,
    float* __restrict__ alpha, float* __restrict__ bar)
{
    extern __shared__ float sm[];
    float* work  = sm;                // 512*34 = 17408 (raw tanh values)
    float* hos   = sm + 17408;        // 512
    float* wps   = hos + 512;         // 32
    float* part  = wps + 32;          // 16
    float* cpart = part + 16;         // 16*33 = 528
    float* ctxa  = cpart + 528;       // 16*32 = 512
    float* wews  = ctxa + 512;        // 128*33 = 4224
    float* webs  = wews + 4224;       // 128
    float* ss    = webs + 128;        // 512 (raw exp values)

    int tid = threadIdx.x;
    int lane = tid & 31, w = tid >> 5;
    int b = blockIdx.x >> 5;
    int i0 = (blockIdx.x & 31) << 4;

    float h1r[32];
    {
        const float4* src = (const float4*)(h1 + ((size_t)b*512 + tid)*32);
#pragma unroll
        for (int q = 0; q < 8; q++) {
            float4 v = src[q];
            h1r[q*4+0]=v.x; h1r[q*4+1]=v.y; h1r[q*4+2]=v.z; h1r[q*4+3]=v.w;
        }
    }
    hos[tid] = ho[((size_t)b*512 + i0)*32 + tid];
    if (tid < 32) wps[tid] = wphi[tid];
    if (tid < 128) webs[tid] = web[tid];
#pragma unroll
    for (int idx = tid; idx < 4096; idx += 512) {
        int hh = idx >> 5, d = idx & 31;
        wews[hh*33 + d] = wew[idx];
    }
    __syncthreads();

    for (int ii = 0; ii < 16; ii++) {
        float t[32];
        float s = 0.f;
        const float* hoi = hos + ii*32;
#pragma unroll
        for (int d = 0; d < 32; d++) {
            t[d] = tanh_approx(hoi[d] + h1r[d]);
            s = fmaf(wps[d], t[d], s);
        }
        float e = __expf(s);
        float es = e;
#pragma unroll
        for (int o = 16; o; o >>= 1) es += __shfl_xor_sync(0xffffffffu, es, o);
        if (lane == 0) part[w] = es;
        ss[tid] = e;
        float2* wr2 = (float2*)(work + tid*34);
#pragma unroll
        for (int d = 0; d < 16; d++) wr2[d] = make_float2(t[2*d], t[2*d+1]);
        __syncthreads();
        float tot = part[0];
#pragma unroll
        for (int q = 1; q < 16; q++) tot += part[q];
        float inv = 1.0f / tot;
        alpha[((size_t)(b*512 + i0 + ii))*512 + tid] = e * inv;
        {
            float acc = 0.f;
            const float* base = work + (w*32)*34 + lane;
            const float* eb = ss + w*32;
#pragma unroll
            for (int k = 0; k < 32; k++) acc = fmaf(eb[k], base[k*34], acc);
            cpart[w*33 + lane] = acc;
        }
        __syncthreads();
        if (tid < 32) {
            float c = 0.f;
#pragma unroll
            for (int q = 0; q < 16; q++) c += cpart[q*33 + tid];
            ctxa[ii*32 + tid] = c * inv;
        }
    }
    __syncthreads();

#pragma unroll
    for (int r = 0; r < 4; r++) {
        int o = tid + r*512;
        int ii = o >> 7, hh = o & 127;
        size_t row = (size_t)b*512 + i0 + ii;
        float v = XA[row*128 + hh] + XAC[row*128 + hh] + webs[hh];
        const float* cw = wews + hh*33;
        const float* cx = ctxa + ii*32;
#pragma unroll
        for (int d = 0; d < 32; d++) v = fmaf(cx[d], cw[d], v);
        bar[row*128 + hh] = v;
    }
}

// ---------------- batched NN GEMM accumulate (FFMA2 inner) --------------------
__global__ __launch_bounds__(256) void gemm_nn_acc(
    const float* __restrict__ al, const float* __restrict__ Bx, float* __restrict__ C)
{
    __shared__ float As[2][32][68];
    __shared__ float Bs[2][32][68];
    int b = blockIdx.z, m0 = blockIdx.x*64, n0 = blockIdx.y*64;
    int tid = threadIdx.x, tx = tid & 15, ty = tid >> 4;
    const float* Ab = al + (size_t)b*512*512;
    const float* Bb = Bx + (size_t)b*512*128;
    unsigned long long accp[4][2];
#pragma unroll
    for (int r = 0; r < 4; r++) { accp[r][0] = 0ull; accp[r][1] = 0ull; }

    float4 av[2], bv[2];
    auto prefetch = [&](int k0) {
#pragma unroll
        for (int i = 0; i < 2; i++) {
            int idx = tid + i*256;
            int mm = idx >> 3, q = idx & 7;
            av[i] = *(const float4*)(Ab + (size_t)(m0+mm)*512 + k0 + q*4);
        }
#pragma unroll
        for (int i = 0; i < 2; i++) {
            int idx = tid + i*256;
            int kk = idx >> 4, q = idx & 15;
            bv[i] = *(const float4*)(Bb + (size_t)(k0+kk)*128 + n0 + q*4);
        }
    };
    auto stash = [&](int buf) {
#pragma unroll
        for (int i = 0; i < 2; i++) {
            int idx = tid + i*256;
            int mm = idx >> 3, q = idx & 7;
            As[buf][q*4+0][mm]=av[i].x; As[buf][q*4+1][mm]=av[i].y;
            As[buf][q*4+2][mm]=av[i].z; As[buf][q*4+3][mm]=av[i].w;
        }
#pragma unroll
        for (int i = 0; i < 2; i++) {
            int idx = tid + i*256;
            int kk = idx >> 4, q = idx & 15;
            *(float4*)&Bs[buf][kk][q*4] = bv[i];
        }
    };

    prefetch(0);
    stash(0);
    __syncthreads();
    for (int kt = 0; kt < 16; kt++) {
        int buf = kt & 1;
        if (kt + 1 < 16) prefetch((kt + 1) << 5);
#pragma unroll
        for (int k = 0; k < 32; k++) {
            float4 a = *(const float4*)&As[buf][k][ty*4];
            ulonglong2 wb = *(const ulonglong2*)&Bs[buf][k][tx*4];
            unsigned long long pa[4];
            pa[0] = pack2(a.x, a.x); pa[1] = pack2(a.y, a.y);
            pa[2] = pack2(a.z, a.z); pa[3] = pack2(a.w, a.w);
#pragma unroll
            for (int r = 0; r < 4; r++) {
                accp[r][0] = ffma2(pa[r], wb.x, accp[r][0]);
                accp[r][1] = ffma2(pa[r], wb.y, accp[r][1]);
            }
        }
        if (kt + 1 < 16) {
            stash(buf ^ 1);
            __syncthreads();
        }
    }
    float* Cb = C + (size_t)b*512*128;
#pragma unroll
    for (int r = 0; r < 4; r++)
#pragma unroll
        for (int cp = 0; cp < 2; cp++) {
            float2 v = unpack2(accp[r][cp]);
            size_t base = (size_t)(m0+ty*4+r)*128 + n0 + tx*4 + cp*2;
            Cb[base]     += v.x;
            Cb[base + 1] += v.y;
        }
}

// ---------------- SE block ---------------------------------------------------
__global__ __launch_bounds__(128) void se_kernel(
    const float* __restrict__ bar, const float* __restrict__ w1,
    const float* __restrict__ b1, const float* __restrict__ w2,
    const float* __restrict__ b2, float* __restrict__ y2)
{
    __shared__ float pooled[128];
    __shared__ float y1s[32];
    int b = blockIdx.x, tid = threadIdx.x;
    const float* base = bar + (size_t)(b << 9)*128 + tid;
    float p = 0.f;
#pragma unroll 8
    for (int n = 0; n < 512; n++) p += base[n*128];
    pooled[tid] = p;
    __syncthreads();
    if (tid < 32) {
        float v = b1[tid];
        const float* wr = w1 + tid*128;
#pragma unroll 8
        for (int h = 0; h < 128; h++) v = fmaf(pooled[h], wr[h], v);
        y1s[tid] = fmaxf(v, 0.f);
    }
    __syncthreads();
    float v = b2[tid];
    const float* wr = w2 + tid*32;
#pragma unroll
    for (int r = 0; r < 32; r++) v = fmaf(y1s[r], wr[r], v);
    y2[b*128 + tid] = __fdividef(1.0f, 1.0f + __expf(-v));
}

// ---------------- head2: out[4096,3] -----------------------------------------
__global__ __launch_bounds__(192) void head2_kernel(
    const float* __restrict__ Hin, const float* __restrict__ W,
    const float* __restrict__ bias, float* __restrict__ out)
{
    __shared__ float Hs[64][68];
    __shared__ float Ws3[192];
    __shared__ float bs[3];
    int tid = threadIdx.x, r0 = blockIdx.x*64;
    for (int idx = tid; idx < 64*16; idx += 192) {
        int m2 = idx >> 4, q = idx & 15;
        *(float4*)&Hs[m2][q*4] = *(const float4*)(Hin + (size_t)(r0+m2)*64 + q*4);
    }
    if (tid < 192) Ws3[tid] = W[tid];
    if (tid < 3) bs[tid] = bias[tid];
    __syncthreads();
    int r = tid/3, o = tid%3;
    float acc = bs[o];
#pragma unroll 8
    for (int k = 0; k < 64; k++) acc = fmaf(Hs[r][k], Ws3[o*64+k], acc);
    out[(size_t)(r0+r)*3 + o] = acc;
}

// ---------------- host orchestration ----------------------------------------
extern "C" void kernel_launch(void* const* d_in, const int* in_sizes, int n_in,
                              void* d_out, int out_size) {
    const float* X       = (const float*)d_in[0];
    const float* A       = (const float*)d_in[1];
    const float* Ac      = (const float*)d_in[2];
    const float* embed_w = (const float*)d_in[3];
    const float* embed_b = (const float*)d_in[4];
    const float* topo_eps= (const float*)d_in[5];
    const float* topo_w  = (const float*)d_in[6];
    const float* topo_b  = (const float*)d_in[7];
    const float* theta   = (const float*)d_in[8];
    const float* gin_eps = (const float*)d_in[9];
    const float* gin_w   = (const float*)d_in[10];
    const float* gin_b   = (const float*)d_in[11];
    const float* wo      = (const float*)d_in[12];
    const float* w1      = (const float*)d_in[13];
    const float* wphi    = (const float*)d_in[14];
    const float* wy_w    = (const float*)d_in[15];
    const float* wy_b    = (const float*)d_in[16];
    const float* we_w    = (const float*)d_in[17];
    const float* we_b    = (const float*)d_in[18];
    const float* lin1_w  = (const float*)d_in[19];
    const float* lin1_b  = (const float*)d_in[20];
    const float* lin2_w  = (const float*)d_in[21];
    const float* lin2_b  = (const float*)d_in[22];
    const float* mlp_w   = (const float*)d_in[23];
    const float* mlp_b   = (const float*)d_in[24];
    const float* head1_w = (const float*)d_in[25];
    const float* head1_b = (const float*)d_in[26];
    const float* head2_w = (const float*)d_in[27];
    const float* head2_b = (const float*)d_in[28];
    float* out = (float*)d_out;

    float* S = nullptr;
    cudaGetSymbolAddress((void**)&S, g_scratch);
    const size_t BIG = 524288;
    float* Xh    = S;
    float* Xp    = S + 1*BIG;
    float* aggA  = S + 2*BIG;
    float* aggAc = S + 3*BIG;
    float* XAb   = S + 4*BIG;
    float* XACb  = S + 5*BIG;
    float* Xy    = S + 6*BIG;
    float* bar   = S + 7*BIG;
    float* hob   = S + 8*BIG;
    float* h1b   = hob + 131072;
    float* alphab= h1b + 131072;
    float* y2b   = alphab + 2097152;
    float* h64   = y2b + 1024;

    const int ATTN_SMEM = (17408 + 512 + 32 + 16 + 528 + 512 + 4224 + 128 + 512) * 4; // 95488
    const int GEMM_SMEM = (2*32*68 + 2*32*132) * 4;   // 51200
    const int HALF_SMEM = (2*32*36 + 2*32*132) * 4;   // 43008
    cudaFuncSetAttribute(attn_kernel, cudaFuncAttributeMaxDynamicSharedMemorySize, ATTN_SMEM);
    cudaFuncSetAttribute(gemm_multi, cudaFuncAttributeMaxDynamicSharedMemorySize, GEMM_SMEM);
    cudaFuncSetAttribute(gemm_half, cudaFuncAttributeMaxDynamicSharedMemorySize, HALF_SMEM);

    build_adj<<<dim3(4096, 2), 128>>>(A, Ac);

    gemm_half<<<128, 256, HALF_SMEM>>>(GJob{X, embed_w, embed_b, Xh, nullptr, 64, 128, 0});
    gin_agg<<<dim3(1024, 2), 128>>>(Xh, aggA, aggAc, topo_eps, topo_eps);
    {
        GJobs js{};
        js.j[0] = GJob{aggA,  topo_w, topo_b, XAb,  nullptr, 128, 128, 1};
        js.j[1] = GJob{aggAc, topo_w, topo_b, XACb, nullptr, 128, 128, 1};
        gemm_multi<<<dim3(64, 2), 256, GEMM_SMEM>>>(js);
    }
    topo_combine<<<2048, 256>>>(Xh, XAb, XACb, theta, Xp);

    for (int l = 0; l < 3; l++) {
        gin_agg<<<dim3(1024, 2), 128>>>(Xp, aggA, aggAc,
                                        gin_eps + l*2, gin_eps + l*2 + 1);
        {
            GJobs js{};
            js.j[0] = GJob{aggA,  gin_w + (size_t)(l*2+0)*16384, gin_b + (l*2+0)*128, XAb,  nullptr, 128, 128, 1};
            js.j[1] = GJob{aggAc, gin_w + (size_t)(l*2+1)*16384, gin_b + (l*2+1)*128, XACb, nullptr, 128, 128, 1};
            js.j[2] = GJob{Xp, wy_w + (size_t)l*16384, wy_b + l*128, Xy, nullptr, 128, 128, 0};
            js.j[3] = GJob{Xp, wo + (size_t)l*4096, nullptr, hob, nullptr, 128, 32, 0};
            js.j[4] = GJob{Xp, w1 + (size_t)l*4096, nullptr, h1b, nullptr, 128, 32, 0};
            gemm_multi<<<dim3(64, 5), 256, GEMM_SMEM>>>(js);
        }
        attn_kernel<<<256, 512, ATTN_SMEM>>>(hob, h1b, wphi + l*32, XAb, XACb,
                                             we_w + (size_t)l*4096, we_b + l*128,
                                             alphab, bar);
        gemm_nn_acc<<<dim3(8, 2, 8), 256>>>(alphab, Xy, bar);
        se_kernel<<<8, 128>>>(bar, lin1_w + (size_t)l*4096, lin1_b + l*32,
                              lin2_w + (size_t)l*4096, lin2_b + l*128, y2b);
        gemm_half<<<128, 256, HALF_SMEM>>>(GJob{bar, mlp_w + (size_t)l*16384, mlp_b + l*128, Xp, y2b, 128, 128, 4});
    }
    gemm_half<<<128, 256, HALF_SMEM>>>(GJob{Xp, head1_w, head1_b, h64, nullptr, 128, 64, 1});
    head2_kernel<<<64, 192>>>(h64, head2_w, head2_b, out);
}

// round 15
// speedup vs baseline: 1.2760x; 1.0795x over previous
#include <cuda_runtime.h>

__device__ float g_scratch[6816768];
__device__ int g_cnt[2 * 4096];
__device__ int g_adj[2 * 4096 * 96];   // stores j*128 (premultiplied)

__device__ __forceinline__ float tanh_fast(float x) {
    float e = __expf(2.0f * x);
    return 1.0f - __fdividef(2.0f, e + 1.0f);
}
__device__ __forceinline__ float tanh_approx(float x) {
    float y; asm("tanh.approx.f32 %0, %1;" : "=f"(y) : "f"(x)); return y;
}

// ---- packed f32x2 helpers (FFMA2) ------------------------------------------
__device__ __forceinline__ unsigned long long pack2(float x, float y) {
    unsigned long long r;
    asm("mov.b64 %0, {%1, %2};" : "=l"(r) : "f"(x), "f"(y));
    return r;
}
__device__ __forceinline__ unsigned long long ffma2(unsigned long long a,
                                                    unsigned long long b,
                                                    unsigned long long c) {
    unsigned long long d;
    asm("fma.rn.f32x2 %0, %1, %2, %3;" : "=l"(d) : "l"(a), "l"(b), "l"(c));
    return d;
}
__device__ __forceinline__ float2 unpack2(unsigned long long v) {
    float2 f;
    asm("mov.b64 {%0, %1}, %2;" : "=f"(f.x), "=f"(f.y) : "l"(v));
    return f;
}

struct GJob { const float* X; const float* W; const float* bias; float* out;
              const float* scale; int K; int NOUT; int flags; };
struct GJobs { GJob j[5]; };

// ---------------- multi-job thin GEMM (64-row tiles, dbl-buffered, FFMA2) ----
template<int CN>
__device__ __forceinline__ void gemm_inner(unsigned long long accp[4][4],
                                           const float Xs[32][68],
                                           const float Ws[32][132], int tx, int ty) {
#pragma unroll
    for (int k = 0; k < 32; k++) {
        float4 a = *(const float4*)&Xs[k][ty*4];
        unsigned long long pa[4];
        pa[0] = pack2(a.x, a.x); pa[1] = pack2(a.y, a.y);
        pa[2] = pack2(a.z, a.z); pa[3] = pack2(a.w, a.w);
        if (CN == 8) {
            ulonglong2 wA = *(const ulonglong2*)&Ws[k][tx*4];
            ulonglong2 wB = *(const ulonglong2*)&Ws[k][64 + tx*4];
#pragma unroll
            for (int r = 0; r < 4; r++) {
                accp[r][0] = ffma2(pa[r], wA.x, accp[r][0]);
                accp[r][1] = ffma2(pa[r], wA.y, accp[r][1]);
                accp[r][2] = ffma2(pa[r], wB.x, accp[r][2]);
                accp[r][3] = ffma2(pa[r], wB.y, accp[r][3]);
            }
        } else if (CN == 4) {
            ulonglong2 wA = *(const ulonglong2*)&Ws[k][tx*4];
#pragma unroll
            for (int r = 0; r < 4; r++) {
                accp[r][0] = ffma2(pa[r], wA.x, accp[r][0]);
                accp[r][1] = ffma2(pa[r], wA.y, accp[r][1]);
            }
        } else {
            unsigned long long wA = *(const unsigned long long*)&Ws[k][tx*2];
#pragma unroll
            for (int r = 0; r < 4; r++)
                accp[r][0] = ffma2(pa[r], wA, accp[r][0]);
        }
    }
}

__global__ __launch_bounds__(256) void gemm_multi(GJobs jobs) {
    GJob jb = jobs.j[blockIdx.y];
    extern __shared__ float dsm[];
    float (*Xs)[32][68]  = (float(*)[32][68])dsm;
    float (*Ws)[32][132] = (float(*)[32][132])(dsm + 2*32*68);
    int tid = threadIdx.x, tx = tid & 15, ty = tid >> 4;
    int r0 = blockIdx.x * 64;
    unsigned long long accp[4][4];
#pragma unroll
    for (int r = 0; r < 4; r++)
#pragma unroll
        for (int c = 0; c < 4; c++) accp[r][c] = 0ull;
    int cn = jb.NOUT >> 4;
    int bsel = r0 >> 9;
    int nw = jb.NOUT << 3;
    int nk = jb.K >> 5;

    float4 xv[2], wv[4];
    int xm2[2], xq[2];
#pragma unroll
    for (int i = 0; i < 2; i++) { int idx = tid + i*256; xm2[i] = idx >> 3; xq[i] = idx & 7; }

    auto prefetch = [&](int kk) {
#pragma unroll
        for (int i = 0; i < 2; i++) {
            float4 v = *(const float4*)(jb.X + (size_t)(r0 + xm2[i])*jb.K + kk + xq[i]*4);
            if (jb.flags & 4) {
                const float* sc = jb.scale + bsel*128 + kk + xq[i]*4;
                v.x *= sc[0]; v.y *= sc[1]; v.z *= sc[2]; v.w *= sc[3];
            }
            xv[i] = v;
        }
#pragma unroll
        for (int i = 0; i < 4; i++) {
            int idx = tid + i*256;
            if (idx < nw) {
                int n2 = idx >> 3, q = idx & 7;
                wv[i] = *(const float4*)(jb.W + (size_t)n2*jb.K + kk + q*4);
            }
        }
    };
    auto stash = [&](int buf) {
#pragma unroll
        for (int i = 0; i < 2; i++) {
            Xs[buf][xq[i]*4+0][xm2[i]] = xv[i].x;
            Xs[buf][xq[i]*4+1][xm2[i]] = xv[i].y;
            Xs[buf][xq[i]*4+2][xm2[i]] = xv[i].z;
            Xs[buf][xq[i]*4+3][xm2[i]] = xv[i].w;
        }
#pragma unroll
        for (int i = 0; i < 4; i++) {
            int idx = tid + i*256;
            if (idx < nw) {
                int n2 = idx >> 3, q = idx & 7;
                Ws[buf][q*4+0][n2] = wv[i].x;
                Ws[buf][q*4+1][n2] = wv[i].y;
                Ws[buf][q*4+2][n2] = wv[i].z;
                Ws[buf][q*4+3][n2] = wv[i].w;
            }
        }
    };

    prefetch(0);
    stash(0);
    __syncthreads();
    for (int kt = 0; kt < nk; kt++) {
        int buf = kt & 1;
        if (kt + 1 < nk) prefetch((kt + 1) << 5);
        if (cn == 8)      gemm_inner<8>(accp, Xs[buf], Ws[buf], tx, ty);
        else if (cn == 4) gemm_inner<4>(accp, Xs[buf], Ws[buf], tx, ty);
        else              gemm_inner<2>(accp, Xs[buf], Ws[buf], tx, ty);
        if (kt + 1 < nk) {
            stash(buf ^ 1);
            __syncthreads();
        }
    }
#pragma unroll
    for (int r = 0; r < 4; r++) {
        int row = r0 + ty*4 + r;
#pragma unroll
        for (int cp = 0; cp < 4; cp++) {
            if (cp >= (cn >> 1)) break;
            int n2;
            if (cn == 8)      n2 = (cp < 2) ? (tx*4 + cp*2) : (64 + tx*4 + (cp-2)*2);
            else if (cn == 4) n2 = tx*4 + cp*2;
            else              n2 = tx*2;
            float2 v = unpack2(accp[r][cp]);
            if (jb.bias) { v.x += jb.bias[n2]; v.y += jb.bias[n2+1]; }
            if (jb.flags & 1) { v.x = fmaxf(v.x, 0.f); v.y = fmaxf(v.y, 0.f); }
            jb.out[(size_t)row*jb.NOUT + n2]     = v.x;
            jb.out[(size_t)row*jb.NOUT + n2 + 1] = v.y;
        }
    }
}

// ---------------- single-job GEMM, 32-row tiles ------------------------------
template<int CN>
__device__ __forceinline__ void gemm_inner_h(unsigned long long accp[2][4],
                                             const float Xs[32][36],
                                             const float Ws[32][132], int tx, int ty) {
#pragma unroll
    for (int k = 0; k < 32; k++) {
        float2 a = *(const float2*)&Xs[k][ty*2];
        unsigned long long pa0 = pack2(a.x, a.x);
        unsigned long long pa1 = pack2(a.y, a.y);
        if (CN == 8) {
            ulonglong2 wA = *(const ulonglong2*)&Ws[k][tx*4];
            ulonglong2 wB = *(const ulonglong2*)&Ws[k][64 + tx*4];
            accp[0][0] = ffma2(pa0, wA.x, accp[0][0]);
            accp[0][1] = ffma2(pa0, wA.y, accp[0][1]);
            accp[0][2] = ffma2(pa0, wB.x, accp[0][2]);
            accp[0][3] = ffma2(pa0, wB.y, accp[0][3]);
            accp[1][0] = ffma2(pa1, wA.x, accp[1][0]);
            accp[1][1] = ffma2(pa1, wA.y, accp[1][1]);
            accp[1][2] = ffma2(pa1, wB.x, accp[1][2]);
            accp[1][3] = ffma2(pa1, wB.y, accp[1][3]);
        } else {
            ulonglong2 wA = *(const ulonglong2*)&Ws[k][tx*4];
            accp[0][0] = ffma2(pa0, wA.x, accp[0][0]);
            accp[0][1] = ffma2(pa0, wA.y, accp[0][1]);
            accp[1][0] = ffma2(pa1, wA.x, accp[1][0]);
            accp[1][1] = ffma2(pa1, wA.y, accp[1][1]);
        }
    }
}

__global__ __launch_bounds__(256) void gemm_half(GJob jb) {
    extern __shared__ float dsm[];
    float (*Xs)[32][36]  = (float(*)[32][36])dsm;
    float (*Ws)[32][132] = (float(*)[32][132])(dsm + 2*32*36);
    int tid = threadIdx.x, tx = tid & 15, ty = tid >> 4;
    int r0 = blockIdx.x * 32;
    unsigned long long accp[2][4];
#pragma unroll
    for (int r = 0; r < 2; r++)
#pragma unroll
        for (int c = 0; c < 4; c++) accp[r][c] = 0ull;
    int cn = jb.NOUT >> 4;
    int bsel = r0 >> 9;
    int nw = jb.NOUT << 3;
    int nk = jb.K >> 5;
    int xm = tid >> 3, xq = tid & 7;

    float4 xv, wv[4];
    auto prefetch = [&](int kk) {
        float4 v = *(const float4*)(jb.X + (size_t)(r0 + xm)*jb.K + kk + xq*4);
        if (jb.flags & 4) {
            const float* sc = jb.scale + bsel*128 + kk + xq*4;
            v.x *= sc[0]; v.y *= sc[1]; v.z *= sc[2]; v.w *= sc[3];
        }
        xv = v;
#pragma unroll
        for (int i = 0; i < 4; i++) {
            int idx = tid + i*256;
            if (idx < nw) {
                int n2 = idx >> 3, q = idx & 7;
                wv[i] = *(const float4*)(jb.W + (size_t)n2*jb.K + kk + q*4);
            }
        }
    };
    auto stash = [&](int buf) {
        Xs[buf][xq*4+0][xm] = xv.x;
        Xs[buf][xq*4+1][xm] = xv.y;
        Xs[buf][xq*4+2][xm] = xv.z;
        Xs[buf][xq*4+3][xm] = xv.w;
#pragma unroll
        for (int i = 0; i < 4; i++) {
            int idx = tid + i*256;
            if (idx < nw) {
                int n2 = idx >> 3, q = idx & 7;
                Ws[buf][q*4+0][n2] = wv[i].x;
                Ws[buf][q*4+1][n2] = wv[i].y;
                Ws[buf][q*4+2][n2] = wv[i].z;
                Ws[buf][q*4+3][n2] = wv[i].w;
            }
        }
    };

    prefetch(0);
    stash(0);
    __syncthreads();
    for (int kt = 0; kt < nk; kt++) {
        int buf = kt & 1;
        if (kt + 1 < nk) prefetch((kt + 1) << 5);
        if (cn == 8) gemm_inner_h<8>(accp, Xs[buf], Ws[buf], tx, ty);
        else         gemm_inner_h<4>(accp, Xs[buf], Ws[buf], tx, ty);
        if (kt + 1 < nk) {
            stash(buf ^ 1);
            __syncthreads();
        }
    }
#pragma unroll
    for (int r = 0; r < 2; r++) {
        int row = r0 + ty*2 + r;
#pragma unroll
        for (int cp = 0; cp < 4; cp++) {
            if (cp >= (cn >> 1)) break;
            int n2;
            if (cn == 8) n2 = (cp < 2) ? (tx*4 + cp*2) : (64 + tx*4 + (cp-2)*2);
            else         n2 = tx*4 + cp*2;
            float2 v = unpack2(accp[r][cp]);
            if (jb.bias) { v.x += jb.bias[n2]; v.y += jb.bias[n2+1]; }
            if (jb.flags & 1) { v.x = fmaxf(v.x, 0.f); v.y = fmaxf(v.y, 0.f); }
            jb.out[(size_t)row*jb.NOUT + n2]     = v.x;
            jb.out[(size_t)row*jb.NOUT + n2 + 1] = v.y;
        }
    }
}

// ---------------- adjacency precompute ---------------------------------------
__global__ __launch_bounds__(128) void build_adj(
    const float* __restrict__ A, const float* __restrict__ Ac)
{
    __shared__ int lst[512];
    __shared__ int cnt;
    int bi = blockIdx.x, g = blockIdx.y;
    const float* M = (g == 0) ? A : Ac;
    int tid = threadIdx.x;
    if (tid == 0) cnt = 0;
    __syncthreads();
    float4 v = *(const float4*)(M + (size_t)bi*512 + tid*4);
    if (v.x != 0.f) lst[atomicAdd(&cnt,1)] = (tid*4+0)*128;
    if (v.y != 0.f) lst[atomicAdd(&cnt,1)] = (tid*4+1)*128;
    if (v.z != 0.f) lst[atomicAdd(&cnt,1)] = (tid*4+2)*128;
    if (v.w != 0.f) lst[atomicAdd(&cnt,1)] = (tid*4+3)*128;
    __syncthreads();
    int n = min(cnt, 96);
    if (tid == 0) g_cnt[g*4096 + bi] = n;
    for (int k = tid; k < n; k += 128) g_adj[(size_t)(g*4096 + bi)*96 + k] = lst[k];
}

// ---------------- sparse GIN aggregation v3 ----------------------------------
__global__ __launch_bounds__(128) void gin_agg(
    const float* __restrict__ X, float* __restrict__ outA, float* __restrict__ outAc,
    const float* __restrict__ epsA, const float* __restrict__ epsAc)
{
    __shared__ int lst[4][96];
    int g = blockIdx.y;
    float* out = (g == 0) ? outA : outAc;
    const float* ep = (g == 0) ? epsA : epsAc;
    int tid = threadIdx.x;
    int local = tid >> 5, lane = tid & 31;
    int bi = blockIdx.x * 4 + local;
    int n = g_cnt[g*4096 + bi];
    for (int k = lane; k < n; k += 32)
        lst[local][k] = g_adj[(size_t)(g*4096 + bi)*96 + k];
    __syncwarp();
    int b = bi >> 9;
    float eps1 = 1.0f + *ep;
    float4 acc = *(const float4*)(X + (size_t)bi*128 + lane*4);
    acc.x *= eps1; acc.y *= eps1; acc.z *= eps1; acc.w *= eps1;
    const float* Xb = X + (size_t)(b << 9)*128 + lane*4;
    const int* ls = lst[local];
    int k = 0;
    for (; k + 4 <= n; k += 4) {
        float4 v0 = *(const float4*)(Xb + ls[k]);
        float4 v1 = *(const float4*)(Xb + ls[k+1]);
        float4 v2 = *(const float4*)(Xb + ls[k+2]);
        float4 v3 = *(const float4*)(Xb + ls[k+3]);
        acc.x += (v0.x + v1.x) + (v2.x + v3.x);
        acc.y += (v0.y + v1.y) + (v2.y + v3.y);
        acc.z += (v0.z + v1.z) + (v2.z + v3.z);
        acc.w += (v0.w + v1.w) + (v2.w + v3.w);
    }
    for (; k < n; k++) {
        float4 v = *(const float4*)(Xb + ls[k]);
        acc.x += v.x; acc.y += v.y; acc.z += v.z; acc.w += v.w;
    }
    *(float4*)(out + (size_t)bi*128 + lane*4) = acc;
}

// ---------------- topo combine ----------------------------------------------
__global__ void topo_combine(const float* __restrict__ Xh, const float* __restrict__ hA,
                             const float* __restrict__ hAC, const float* __restrict__ theta,
                             float* __restrict__ Xp)
{
    int idx = blockIdx.x*256 + threadIdx.x;
    int h = idx & 127;
    Xp[idx] = Xh[idx] + tanh_fast(hA[idx]*theta[2*h]) + tanh_fast(hAC[idx]*theta[2*h+1]);
}

// ---------------- fused flexible attention v6: 2 blocks/SM -------------------
// t no longer kept in registers; written to smem inside the score loop.
__global__ __launch_bounds__(512, 2) void attn_kernel(
    const float* __restrict__ ho, const float* __restrict__ h1,
    const float* __restrict__ wphi,
    const float* __restrict__ XA, const float* __restrict__ XAC,
    const float* __restrict__ wew, const float* __restrict__ web,
    float* __restrict__ alpha, float* __restrict__ bar)
{
    extern __shared__ float sm[];
    float* work  = sm;                // 512*34 = 17408 (raw tanh values)
    float* hos   = sm + 17408;        // 512
    float* wps   = hos + 512;         // 32
    float* part  = wps + 32;          // 16
    float* cpart = part + 16;         // 16*33 = 528
    float* ctxa  = cpart + 528;       // 16*32 = 512
    float* wews  = ctxa + 512;        // 128*33 = 4224
    float* webs  = wews + 4224;       // 128
    float* ss    = webs + 128;        // 512 (raw exp values)

    int tid = threadIdx.x;
    int lane = tid & 31, w = tid >> 5;
    int b = blockIdx.x >> 5;
    int i0 = (blockIdx.x & 31) << 4;

    float h1r[32];
    {
        const float4* src = (const float4*)(h1 + ((size_t)b*512 + tid)*32);
#pragma unroll
        for (int q = 0; q < 8; q++) {
            float4 v = src[q];
            h1r[q*4+0]=v.x; h1r[q*4+1]=v.y; h1r[q*4+2]=v.z; h1r[q*4+3]=v.w;
        }
    }
    hos[tid] = ho[((size_t)b*512 + i0)*32 + tid];
    if (tid < 32) wps[tid] = wphi[tid];
    if (tid < 128) webs[tid] = web[tid];
#pragma unroll
    for (int idx = tid; idx < 4096; idx += 512) {
        int hh = idx >> 5, d = idx & 31;
        wews[hh*33 + d] = wew[idx];
    }
    __syncthreads();

    for (int ii = 0; ii < 16; ii++) {
        float s = 0.f;
        const float* hoi = hos + ii*32;
        float2* wr2 = (float2*)(work + tid*34);
#pragma unroll
        for (int d2 = 0; d2 < 16; d2++) {
            float t0 = tanh_approx(hoi[2*d2]   + h1r[2*d2]);
            float t1 = tanh_approx(hoi[2*d2+1] + h1r[2*d2+1]);
            s = fmaf(wps[2*d2],   t0, s);
            s = fmaf(wps[2*d2+1], t1, s);
            wr2[d2] = make_float2(t0, t1);
        }
        float e = __expf(s);
        float es = e;
#pragma unroll
        for (int o = 16; o; o >>= 1) es += __shfl_xor_sync(0xffffffffu, es, o);
        if (lane == 0) part[w] = es;
        ss[tid] = e;
        __syncthreads();
        float tot = part[0];
#pragma unroll
        for (int q = 1; q < 16; q++) tot += part[q];
        float inv = 1.0f / tot;
        alpha[((size_t)(b*512 + i0 + ii))*512 + tid] = e * inv;
        {
            float acc = 0.f;
            const float* base = work + (w*32)*34 + lane;
            const float* eb = ss + w*32;
#pragma unroll
            for (int k = 0; k < 32; k++) acc = fmaf(eb[k], base[k*34], acc);
            cpart[w*33 + lane] = acc;
        }
        __syncthreads();
        if (tid < 32) {
            float c = 0.f;
#pragma unroll
            for (int q = 0; q < 16; q++) c += cpart[q*33 + tid];
            ctxa[ii*32 + tid] = c * inv;
        }
    }
    __syncthreads();

#pragma unroll
    for (int r = 0; r < 4; r++) {
        int o = tid + r*512;
        int ii = o >> 7, hh = o & 127;
        size_t row = (size_t)b*512 + i0 + ii;
        float v = XA[row*128 + hh] + XAC[row*128 + hh] + webs[hh];
        const float* cw = wews + hh*33;
        const float* cx = ctxa + ii*32;
#pragma unroll
        for (int d = 0; d < 32; d++) v = fmaf(cx[d], cw[d], v);
        bar[row*128 + hh] = v;
    }
}

// ---------------- batched NN GEMM accumulate (FFMA2 inner) --------------------
__global__ __launch_bounds__(256) void gemm_nn_acc(
    const float* __restrict__ al, const float* __restrict__ Bx, float* __restrict__ C)
{
    __shared__ float As[2][32][68];
    __shared__ float Bs[2][32][68];
    int b = blockIdx.z, m0 = blockIdx.x*64, n0 = blockIdx.y*64;
    int tid = threadIdx.x, tx = tid & 15, ty = tid >> 4;
    const float* Ab = al + (size_t)b*512*512;
    const float* Bb = Bx + (size_t)b*512*128;
    unsigned long long accp[4][2];
#pragma unroll
    for (int r = 0; r < 4; r++) { accp[r][0] = 0ull; accp[r][1] = 0ull; }

    float4 av[2], bv[2];
    auto prefetch = [&](int k0) {
#pragma unroll
        for (int i = 0; i < 2; i++) {
            int idx = tid + i*256;
            int mm = idx >> 3, q = idx & 7;
            av[i] = *(const float4*)(Ab + (size_t)(m0+mm)*512 + k0 + q*4);
        }
#pragma unroll
        for (int i = 0; i < 2; i++) {
            int idx = tid + i*256;
            int kk = idx >> 4, q = idx & 15;
            bv[i] = *(const float4*)(Bb + (size_t)(k0+kk)*128 + n0 + q*4);
        }
    };
    auto stash = [&](int buf) {
#pragma unroll
        for (int i = 0; i < 2; i++) {
            int idx = tid + i*256;
            int mm = idx >> 3, q = idx & 7;
            As[buf][q*4+0][mm]=av[i].x; As[buf][q*4+1][mm]=av[i].y;
            As[buf][q*4+2][mm]=av[i].z; As[buf][q*4+3][mm]=av[i].w;
        }
#pragma unroll
        for (int i = 0; i < 2; i++) {
            int idx = tid + i*256;
            int kk = idx >> 4, q = idx & 15;
            *(float4*)&Bs[buf][kk][q*4] = bv[i];
        }
    };

    prefetch(0);
    stash(0);
    __syncthreads();
    for (int kt = 0; kt < 16; kt++) {
        int buf = kt & 1;
        if (kt + 1 < 16) prefetch((kt + 1) << 5);
#pragma unroll
        for (int k = 0; k < 32; k++) {
            float4 a = *(const float4*)&As[buf][k][ty*4];
            ulonglong2 wb = *(const ulonglong2*)&Bs[buf][k][tx*4];
            unsigned long long pa[4];
            pa[0] = pack2(a.x, a.x); pa[1] = pack2(a.y, a.y);
            pa[2] = pack2(a.z, a.z); pa[3] = pack2(a.w, a.w);
#pragma unroll
            for (int r = 0; r < 4; r++) {
                accp[r][0] = ffma2(pa[r], wb.x, accp[r][0]);
                accp[r][1] = ffma2(pa[r], wb.y, accp[r][1]);
            }
        }
        if (kt + 1 < 16) {
            stash(buf ^ 1);
            __syncthreads();
        }
    }
    float* Cb = C + (size_t)b*512*128;
#pragma unroll
    for (int r = 0; r < 4; r++)
#pragma unroll
        for (int cp = 0; cp < 2; cp++) {
            float2 v = unpack2(accp[r][cp]);
            size_t base = (size_t)(m0+ty*4+r)*128 + n0 + tx*4 + cp*2;
            Cb[base]     += v.x;
            Cb[base + 1] += v.y;
        }
}

// ---------------- SE block ---------------------------------------------------
__global__ __launch_bounds__(128) void se_kernel(
    const float* __restrict__ bar, const float* __restrict__ w1,
    const float* __restrict__ b1, const float* __restrict__ w2,
    const float* __restrict__ b2, float* __restrict__ y2)
{
    __shared__ float pooled[128];
    __shared__ float y1s[32];
    int b = blockIdx.x, tid = threadIdx.x;
    const float* base = bar + (size_t)(b << 9)*128 + tid;
    float p = 0.f;
#pragma unroll 8
    for (int n = 0; n < 512; n++) p += base[n*128];
    pooled[tid] = p;
    __syncthreads();
    if (tid < 32) {
        float v = b1[tid];
        const float* wr = w1 + tid*128;
#pragma unroll 8
        for (int h = 0; h < 128; h++) v = fmaf(pooled[h], wr[h], v);
        y1s[tid] = fmaxf(v, 0.f);
    }
    __syncthreads();
    float v = b2[tid];
    const float* wr = w2 + tid*32;
#pragma unroll
    for (int r = 0; r < 32; r++) v = fmaf(y1s[r], wr[r], v);
    y2[b*128 + tid] = __fdividef(1.0f, 1.0f + __expf(-v));
}

// ---------------- head2: out[4096,3] -----------------------------------------
__global__ __launch_bounds__(192) void head2_kernel(
    const float* __restrict__ Hin, const float* __restrict__ W,
    const float* __restrict__ bias, float* __restrict__ out)
{
    __shared__ float Hs[64][68];
    __shared__ float Ws3[192];
    __shared__ float bs[3];
    int tid = threadIdx.x, r0 = blockIdx.x*64;
    for (int idx = tid; idx < 64*16; idx += 192) {
        int m2 = idx >> 4, q = idx & 15;
        *(float4*)&Hs[m2][q*4] = *(const float4*)(Hin + (size_t)(r0+m2)*64 + q*4);
    }
    if (tid < 192) Ws3[tid] = W[tid];
    if (tid < 3) bs[tid] = bias[tid];
    __syncthreads();
    int r = tid/3, o = tid%3;
    float acc = bs[o];
#pragma unroll 8
    for (int k = 0; k < 64; k++) acc = fmaf(Hs[r][k], Ws3[o*64+k], acc);
    out[(size_t)(r0+r)*3 + o] = acc;
}

// ---------------- host orchestration ----------------------------------------
extern "C" void kernel_launch(void* const* d_in, const int* in_sizes, int n_in,
                              void* d_out, int out_size) {
    const float* X       = (const float*)d_in[0];
    const float* A       = (const float*)d_in[1];
    const float* Ac      = (const float*)d_in[2];
    const float* embed_w = (const float*)d_in[3];
    const float* embed_b = (const float*)d_in[4];
    const float* topo_eps= (const float*)d_in[5];
    const float* topo_w  = (const float*)d_in[6];
    const float* topo_b  = (const float*)d_in[7];
    const float* theta   = (const float*)d_in[8];
    const float* gin_eps = (const float*)d_in[9];
    const float* gin_w   = (const float*)d_in[10];
    const float* gin_b   = (const float*)d_in[11];
    const float* wo      = (const float*)d_in[12];
    const float* w1      = (const float*)d_in[13];
    const float* wphi    = (const float*)d_in[14];
    const float* wy_w    = (const float*)d_in[15];
    const float* wy_b    = (const float*)d_in[16];
    const float* we_w    = (const float*)d_in[17];
    const float* we_b    = (const float*)d_in[18];
    const float* lin1_w  = (const float*)d_in[19];
    const float* lin1_b  = (const float*)d_in[20];
    const float* lin2_w  = (const float*)d_in[21];
    const float* lin2_b  = (const float*)d_in[22];
    const float* mlp_w   = (const float*)d_in[23];
    const float* mlp_b   = (const float*)d_in[24];
    const float* head1_w = (const float*)d_in[25];
    const float* head1_b = (const float*)d_in[26];
    const float* head2_w = (const float*)d_in[27];
    const float* head2_b = (const float*)d_in[28];
    float* out = (float*)d_out;

    float* S = nullptr;
    cudaGetSymbolAddress((void**)&S, g_scratch);
    const size_t BIG = 524288;
    float* Xh    = S;
    float* Xp    = S + 1*BIG;
    float* aggA  = S + 2*BIG;
    float* aggAc = S + 3*BIG;
    float* XAb   = S + 4*BIG;
    float* XACb  = S + 5*BIG;
    float* Xy    = S + 6*BIG;
    float* bar   = S + 7*BIG;
    float* hob   = S + 8*BIG;
    float* h1b   = hob + 131072;
    float* alphab= h1b + 131072;
    float* y2b   = alphab + 2097152;
    float* h64   = y2b + 1024;

    const int ATTN_SMEM = (17408 + 512 + 32 + 16 + 528 + 512 + 4224 + 128 + 512) * 4; // 95488
    const int GEMM_SMEM = (2*32*68 + 2*32*132) * 4;   // 51200
    const int HALF_SMEM = (2*32*36 + 2*32*132) * 4;   // 43008
    cudaFuncSetAttribute(attn_kernel, cudaFuncAttributeMaxDynamicSharedMemorySize, ATTN_SMEM);
    cudaFuncSetAttribute(gemm_multi, cudaFuncAttributeMaxDynamicSharedMemorySize, GEMM_SMEM);
    cudaFuncSetAttribute(gemm_half, cudaFuncAttributeMaxDynamicSharedMemorySize, HALF_SMEM);

    build_adj<<<dim3(4096, 2), 128>>>(A, Ac);

    gemm_half<<<128, 256, HALF_SMEM>>>(GJob{X, embed_w, embed_b, Xh, nullptr, 64, 128, 0});
    gin_agg<<<dim3(1024, 2), 128>>>(Xh, aggA, aggAc, topo_eps, topo_eps);
    {
        GJobs js{};
        js.j[0] = GJob{aggA,  topo_w, topo_b, XAb,  nullptr, 128, 128, 1};
        js.j[1] = GJob{aggAc, topo_w, topo_b, XACb, nullptr, 128, 128, 1};
        gemm_multi<<<dim3(64, 2), 256, GEMM_SMEM>>>(js);
    }
    topo_combine<<<2048, 256>>>(Xh, XAb, XACb, theta, Xp);

    for (int l = 0; l < 3; l++) {
        gin_agg<<<dim3(1024, 2), 128>>>(Xp, aggA, aggAc,
                                        gin_eps + l*2, gin_eps + l*2 + 1);
        {
            GJobs js{};
            js.j[0] = GJob{aggA,  gin_w + (size_t)(l*2+0)*16384, gin_b + (l*2+0)*128, XAb,  nullptr, 128, 128, 1};
            js.j[1] = GJob{aggAc, gin_w + (size_t)(l*2+1)*16384, gin_b + (l*2+1)*128, XACb, nullptr, 128, 128, 1};
            js.j[2] = GJob{Xp, wy_w + (size_t)l*16384, wy_b + l*128, Xy, nullptr, 128, 128, 0};
            js.j[3] = GJob{Xp, wo + (size_t)l*4096, nullptr, hob, nullptr, 128, 32, 0};
            js.j[4] = GJob{Xp, w1 + (size_t)l*4096, nullptr, h1b, nullptr, 128, 32, 0};
            gemm_multi<<<dim3(64, 5), 256, GEMM_SMEM>>>(js);
        }
        attn_kernel<<<256, 512, ATTN_SMEM>>>(hob, h1b, wphi + l*32, XAb, XACb,
                                             we_w + (size_t)l*4096, we_b + l*128,
                                             alphab, bar);
        gemm_nn_acc<<<dim3(8, 2, 8), 256>>>(alphab, Xy, bar);
        se_kernel<<<8, 128>>>(bar, lin1_w + (size_t)l*4096, lin1_b + l*32,
                              lin2_w + (size_t)l*4096, lin2_b + l*128, y2b);
        gemm_half<<<128, 256, HALF_SMEM>>>(GJob{bar, mlp_w + (size_t)l*16384, mlp_b + l*128, Xp, y2b, 128, 128, 4});
    }
    gemm_half<<<128, 256, HALF_SMEM>>>(GJob{Xp, head1_w, head1_b, h64, nullptr, 128, 64, 1});
    head2_kernel<<<64, 192>>>(h64, head2_w, head2_b, out);
}

// round 16
// speedup vs baseline: 1.2889x; 1.0101x over previous
#include <cuda_runtime.h>

__device__ float g_scratch[6816768];
__device__ int g_cnt[2 * 4096];
__device__ int g_adj[2 * 4096 * 96];   // stores j*128 (premultiplied)

__device__ __forceinline__ float tanh_fast(float x) {
    float e = __expf(2.0f * x);
    return 1.0f - __fdividef(2.0f, e + 1.0f);
}
__device__ __forceinline__ float tanh_approx(float x) {
    float y; asm("tanh.approx.f32 %0, %1;" : "=f"(y) : "f"(x)); return y;
}

// ---- packed f32x2 helpers (FFMA2) ------------------------------------------
__device__ __forceinline__ unsigned long long pack2(float x, float y) {
    unsigned long long r;
    asm("mov.b64 %0, {%1, %2};" : "=l"(r) : "f"(x), "f"(y));
    return r;
}
__device__ __forceinline__ unsigned long long ffma2(unsigned long long a,
                                                    unsigned long long b,
                                                    unsigned long long c) {
    unsigned long long d;
    asm("fma.rn.f32x2 %0, %1, %2, %3;" : "=l"(d) : "l"(a), "l"(b), "l"(c));
    return d;
}
__device__ __forceinline__ float2 unpack2(unsigned long long v) {
    float2 f;
    asm("mov.b64 {%0, %1}, %2;" : "=f"(f.x), "=f"(f.y) : "l"(v));
    return f;
}

struct GJob { const float* X; const float* W; const float* bias; float* out;
              const float* scale; int K; int NOUT; int flags; };
struct GJobs { GJob j[5]; };

// ---------------- multi-job thin GEMM (64-row tiles, dbl-buffered, FFMA2) ----
template<int CN>
__device__ __forceinline__ void gemm_inner(unsigned long long accp[4][4],
                                           const float Xs[32][68],
                                           const float Ws[32][132], int tx, int ty) {
#pragma unroll
    for (int k = 0; k < 32; k++) {
        float4 a = *(const float4*)&Xs[k][ty*4];
        unsigned long long pa[4];
        pa[0] = pack2(a.x, a.x); pa[1] = pack2(a.y, a.y);
        pa[2] = pack2(a.z, a.z); pa[3] = pack2(a.w, a.w);
        if (CN == 8) {
            ulonglong2 wA = *(const ulonglong2*)&Ws[k][tx*4];
            ulonglong2 wB = *(const ulonglong2*)&Ws[k][64 + tx*4];
#pragma unroll
            for (int r = 0; r < 4; r++) {
                accp[r][0] = ffma2(pa[r], wA.x, accp[r][0]);
                accp[r][1] = ffma2(pa[r], wA.y, accp[r][1]);
                accp[r][2] = ffma2(pa[r], wB.x, accp[r][2]);
                accp[r][3] = ffma2(pa[r], wB.y, accp[r][3]);
            }
        } else if (CN == 4) {
            ulonglong2 wA = *(const ulonglong2*)&Ws[k][tx*4];
#pragma unroll
            for (int r = 0; r < 4; r++) {
                accp[r][0] = ffma2(pa[r], wA.x, accp[r][0]);
                accp[r][1] = ffma2(pa[r], wA.y, accp[r][1]);
            }
        } else {
            unsigned long long wA = *(const unsigned long long*)&Ws[k][tx*2];
#pragma unroll
            for (int r = 0; r < 4; r++)
                accp[r][0] = ffma2(pa[r], wA, accp[r][0]);
        }
    }
}

__global__ __launch_bounds__(256, 2) void gemm_multi(GJobs jobs) {
    GJob jb = jobs.j[blockIdx.y];
    extern __shared__ float dsm[];
    float (*Xs)[32][68]  = (float(*)[32][68])dsm;
    float (*Ws)[32][132] = (float(*)[32][132])(dsm + 2*32*68);
    int tid = threadIdx.x, tx = tid & 15, ty = tid >> 4;
    int r0 = blockIdx.x * 64;
    unsigned long long accp[4][4];
#pragma unroll
    for (int r = 0; r < 4; r++)
#pragma unroll
        for (int c = 0; c < 4; c++) accp[r][c] = 0ull;
    int cn = jb.NOUT >> 4;
    int bsel = r0 >> 9;
    int nw = jb.NOUT << 3;
    int nk = jb.K >> 5;

    float4 xv[2], wv[4];
    int xm2[2], xq[2];
#pragma unroll
    for (int i = 0; i < 2; i++) { int idx = tid + i*256; xm2[i] = idx >> 3; xq[i] = idx & 7; }

    auto prefetch = [&](int kk) {
#pragma unroll
        for (int i = 0; i < 2; i++) {
            float4 v = *(const float4*)(jb.X + (size_t)(r0 + xm2[i])*jb.K + kk + xq[i]*4);
            if (jb.flags & 4) {
                const float* sc = jb.scale + bsel*128 + kk + xq[i]*4;
                v.x *= sc[0]; v.y *= sc[1]; v.z *= sc[2]; v.w *= sc[3];
            }
            xv[i] = v;
        }
#pragma unroll
        for (int i = 0; i < 4; i++) {
            int idx = tid + i*256;
            if (idx < nw) {
                int n2 = idx >> 3, q = idx & 7;
                wv[i] = *(const float4*)(jb.W + (size_t)n2*jb.K + kk + q*4);
            }
        }
    };
    auto stash = [&](int buf) {
#pragma unroll
        for (int i = 0; i < 2; i++) {
            Xs[buf][xq[i]*4+0][xm2[i]] = xv[i].x;
            Xs[buf][xq[i]*4+1][xm2[i]] = xv[i].y;
            Xs[buf][xq[i]*4+2][xm2[i]] = xv[i].z;
            Xs[buf][xq[i]*4+3][xm2[i]] = xv[i].w;
        }
#pragma unroll
        for (int i = 0; i < 4; i++) {
            int idx = tid + i*256;
            if (idx < nw) {
                int n2 = idx >> 3, q = idx & 7;
                Ws[buf][q*4+0][n2] = wv[i].x;
                Ws[buf][q*4+1][n2] = wv[i].y;
                Ws[buf][q*4+2][n2] = wv[i].z;
                Ws[buf][q*4+3][n2] = wv[i].w;
            }
        }
    };

    prefetch(0);
    stash(0);
    __syncthreads();
    for (int kt = 0; kt < nk; kt++) {
        int buf = kt & 1;
        if (kt + 1 < nk) prefetch((kt + 1) << 5);
        if (cn == 8)      gemm_inner<8>(accp, Xs[buf], Ws[buf], tx, ty);
        else if (cn == 4) gemm_inner<4>(accp, Xs[buf], Ws[buf], tx, ty);
        else              gemm_inner<2>(accp, Xs[buf], Ws[buf], tx, ty);
        if (kt + 1 < nk) {
            stash(buf ^ 1);
            __syncthreads();
        }
    }
#pragma unroll
    for (int r = 0; r < 4; r++) {
        int row = r0 + ty*4 + r;
#pragma unroll
        for (int cp = 0; cp < 4; cp++) {
            if (cp >= (cn >> 1)) break;
            int n2;
            if (cn == 8)      n2 = (cp < 2) ? (tx*4 + cp*2) : (64 + tx*4 + (cp-2)*2);
            else if (cn == 4) n2 = tx*4 + cp*2;
            else              n2 = tx*2;
            float2 v = unpack2(accp[r][cp]);
            if (jb.bias) { v.x += jb.bias[n2]; v.y += jb.bias[n2+1]; }
            if (jb.flags & 1) { v.x = fmaxf(v.x, 0.f); v.y = fmaxf(v.y, 0.f); }
            jb.out[(size_t)row*jb.NOUT + n2]     = v.x;
            jb.out[(size_t)row*jb.NOUT + n2 + 1] = v.y;
        }
    }
}

// ---------------- single-job GEMM, 32-row tiles ------------------------------
template<int CN>
__device__ __forceinline__ void gemm_inner_h(unsigned long long accp[2][4],
                                             const float Xs[32][36],
                                             const float Ws[32][132], int tx, int ty) {
#pragma unroll
    for (int k = 0; k < 32; k++) {
        float2 a = *(const float2*)&Xs[k][ty*2];
        unsigned long long pa0 = pack2(a.x, a.x);
        unsigned long long pa1 = pack2(a.y, a.y);
        if (CN == 8) {
            ulonglong2 wA = *(const ulonglong2*)&Ws[k][tx*4];
            ulonglong2 wB = *(const ulonglong2*)&Ws[k][64 + tx*4];
            accp[0][0] = ffma2(pa0, wA.x, accp[0][0]);
            accp[0][1] = ffma2(pa0, wA.y, accp[0][1]);
            accp[0][2] = ffma2(pa0, wB.x, accp[0][2]);
            accp[0][3] = ffma2(pa0, wB.y, accp[0][3]);
            accp[1][0] = ffma2(pa1, wA.x, accp[1][0]);
            accp[1][1] = ffma2(pa1, wA.y, accp[1][1]);
            accp[1][2] = ffma2(pa1, wB.x, accp[1][2]);
            accp[1][3] = ffma2(pa1, wB.y, accp[1][3]);
        } else {
            ulonglong2 wA = *(const ulonglong2*)&Ws[k][tx*4];
            accp[0][0] = ffma2(pa0, wA.x, accp[0][0]);
            accp[0][1] = ffma2(pa0, wA.y, accp[0][1]);
            accp[1][0] = ffma2(pa1, wA.x, accp[1][0]);
            accp[1][1] = ffma2(pa1, wA.y, accp[1][1]);
        }
    }
}

__global__ __launch_bounds__(256) void gemm_half(GJob jb) {
    extern __shared__ float dsm[];
    float (*Xs)[32][36]  = (float(*)[32][36])dsm;
    float (*Ws)[32][132] = (float(*)[32][132])(dsm + 2*32*36);
    int tid = threadIdx.x, tx = tid & 15, ty = tid >> 4;
    int r0 = blockIdx.x * 32;
    unsigned long long accp[2][4];
#pragma unroll
    for (int r = 0; r < 2; r++)
#pragma unroll
        for (int c = 0; c < 4; c++) accp[r][c] = 0ull;
    int cn = jb.NOUT >> 4;
    int bsel = r0 >> 9;
    int nw = jb.NOUT << 3;
    int nk = jb.K >> 5;
    int xm = tid >> 3, xq = tid & 7;

    float4 xv, wv[4];
    auto prefetch = [&](int kk) {
        float4 v = *(const float4*)(jb.X + (size_t)(r0 + xm)*jb.K + kk + xq*4);
        if (jb.flags & 4) {
            const float* sc = jb.scale + bsel*128 + kk + xq*4;
            v.x *= sc[0]; v.y *= sc[1]; v.z *= sc[2]; v.w *= sc[3];
        }
        xv = v;
#pragma unroll
        for (int i = 0; i < 4; i++) {
            int idx = tid + i*256;
            if (idx < nw) {
                int n2 = idx >> 3, q = idx & 7;
                wv[i] = *(const float4*)(jb.W + (size_t)n2*jb.K + kk + q*4);
            }
        }
    };
    auto stash = [&](int buf) {
        Xs[buf][xq*4+0][xm] = xv.x;
        Xs[buf][xq*4+1][xm] = xv.y;
        Xs[buf][xq*4+2][xm] = xv.z;
        Xs[buf][xq*4+3][xm] = xv.w;
#pragma unroll
        for (int i = 0; i < 4; i++) {
            int idx = tid + i*256;
            if (idx < nw) {
                int n2 = idx >> 3, q = idx & 7;
                Ws[buf][q*4+0][n2] = wv[i].x;
                Ws[buf][q*4+1][n2] = wv[i].y;
                Ws[buf][q*4+2][n2] = wv[i].z;
                Ws[buf][q*4+3][n2] = wv[i].w;
            }
        }
    };

    prefetch(0);
    stash(0);
    __syncthreads();
    for (int kt = 0; kt < nk; kt++) {
        int buf = kt & 1;
        if (kt + 1 < nk) prefetch((kt + 1) << 5);
        if (cn == 8) gemm_inner_h<8>(accp, Xs[buf], Ws[buf], tx, ty);
        else         gemm_inner_h<4>(accp, Xs[buf], Ws[buf], tx, ty);
        if (kt + 1 < nk) {
            stash(buf ^ 1);
            __syncthreads();
        }
    }
#pragma unroll
    for (int r = 0; r < 2; r++) {
        int row = r0 + ty*2 + r;
#pragma unroll
        for (int cp = 0; cp < 4; cp++) {
            if (cp >= (cn >> 1)) break;
            int n2;
            if (cn == 8) n2 = (cp < 2) ? (tx*4 + cp*2) : (64 + tx*4 + (cp-2)*2);
            else         n2 = tx*4 + cp*2;
            float2 v = unpack2(accp[r][cp]);
            if (jb.bias) { v.x += jb.bias[n2]; v.y += jb.bias[n2+1]; }
            if (jb.flags & 1) { v.x = fmaxf(v.x, 0.f); v.y = fmaxf(v.y, 0.f); }
            jb.out[(size_t)row*jb.NOUT + n2]     = v.x;
            jb.out[(size_t)row*jb.NOUT + n2 + 1] = v.y;
        }
    }
}

// ---------------- adjacency precompute ---------------------------------------
__global__ __launch_bounds__(128) void build_adj(
    const float* __restrict__ A, const float* __restrict__ Ac)
{
    __shared__ int lst[512];
    __shared__ int cnt;
    int bi = blockIdx.x, g = blockIdx.y;
    const float* M = (g == 0) ? A : Ac;
    int tid = threadIdx.x;
    if (tid == 0) cnt = 0;
    __syncthreads();
    float4 v = *(const float4*)(M + (size_t)bi*512 + tid*4);
    if (v.x != 0.f) lst[atomicAdd(&cnt,1)] = (tid*4+0)*128;
    if (v.y != 0.f) lst[atomicAdd(&cnt,1)] = (tid*4+1)*128;
    if (v.z != 0.f) lst[atomicAdd(&cnt,1)] = (tid*4+2)*128;
    if (v.w != 0.f) lst[atomicAdd(&cnt,1)] = (tid*4+3)*128;
    __syncthreads();
    int n = min(cnt, 96);
    if (tid == 0) g_cnt[g*4096 + bi] = n;
    for (int k = tid; k < n; k += 128) g_adj[(size_t)(g*4096 + bi)*96 + k] = lst[k];
}

// ---------------- sparse GIN aggregation v3 ----------------------------------
__global__ __launch_bounds__(128) void gin_agg(
    const float* __restrict__ X, float* __restrict__ outA, float* __restrict__ outAc,
    const float* __restrict__ epsA, const float* __restrict__ epsAc)
{
    __shared__ int lst[4][96];
    int g = blockIdx.y;
    float* out = (g == 0) ? outA : outAc;
    const float* ep = (g == 0) ? epsA : epsAc;
    int tid = threadIdx.x;
    int local = tid >> 5, lane = tid & 31;
    int bi = blockIdx.x * 4 + local;
    int n = g_cnt[g*4096 + bi];
    for (int k = lane; k < n; k += 32)
        lst[local][k] = g_adj[(size_t)(g*4096 + bi)*96 + k];
    __syncwarp();
    int b = bi >> 9;
    float eps1 = 1.0f + *ep;
    float4 acc = *(const float4*)(X + (size_t)bi*128 + lane*4);
    acc.x *= eps1; acc.y *= eps1; acc.z *= eps1; acc.w *= eps1;
    const float* Xb = X + (size_t)(b << 9)*128 + lane*4;
    const int* ls = lst[local];
    int k = 0;
    for (; k + 4 <= n; k += 4) {
        float4 v0 = *(const float4*)(Xb + ls[k]);
        float4 v1 = *(const float4*)(Xb + ls[k+1]);
        float4 v2 = *(const float4*)(Xb + ls[k+2]);
        float4 v3 = *(const float4*)(Xb + ls[k+3]);
        acc.x += (v0.x + v1.x) + (v2.x + v3.x);
        acc.y += (v0.y + v1.y) + (v2.y + v3.y);
        acc.z += (v0.z + v1.z) + (v2.z + v3.z);
        acc.w += (v0.w + v1.w) + (v2.w + v3.w);
    }
    for (; k < n; k++) {
        float4 v = *(const float4*)(Xb + ls[k]);
        acc.x += v.x; acc.y += v.y; acc.z += v.z; acc.w += v.w;
    }
    *(float4*)(out + (size_t)bi*128 + lane*4) = acc;
}

// ---------------- topo combine ----------------------------------------------
__global__ void topo_combine(const float* __restrict__ Xh, const float* __restrict__ hA,
                             const float* __restrict__ hAC, const float* __restrict__ theta,
                             float* __restrict__ Xp)
{
    int idx = blockIdx.x*256 + threadIdx.x;
    int h = idx & 127;
    Xp[idx] = Xh[idx] + tanh_fast(hA[idx]*theta[2*h]) + tanh_fast(hAC[idx]*theta[2*h+1]);
}

// ---------------- fused flexible attention v6: 2 blocks/SM -------------------
__global__ __launch_bounds__(512, 2) void attn_kernel(
    const float* __restrict__ ho, const float* __restrict__ h1,
    const float* __restrict__ wphi,
    const float* __restrict__ XA, const float* __restrict__ XAC,
    const float* __restrict__ wew, const float* __restrict__ web,
    float* __restrict__ alpha, float* __restrict__ bar)
{
    extern __shared__ float sm[];
    float* work  = sm;                // 512*34 = 17408 (raw tanh values)
    float* hos   = sm + 17408;        // 512
    float* wps   = hos + 512;         // 32
    float* part  = wps + 32;          // 16
    float* cpart = part + 16;         // 16*33 = 528
    float* ctxa  = cpart + 528;       // 16*32 = 512
    float* wews  = ctxa + 512;        // 128*33 = 4224
    float* webs  = wews + 4224;       // 128
    float* ss    = webs + 128;        // 512 (raw exp values)

    int tid = threadIdx.x;
    int lane = tid & 31, w = tid >> 5;
    int b = blockIdx.x >> 5;
    int i0 = (blockIdx.x & 31) << 4;

    float h1r[32];
    {
        const float4* src = (const float4*)(h1 + ((size_t)b*512 + tid)*32);
#pragma unroll
        for (int q = 0; q < 8; q++) {
            float4 v = src[q];
            h1r[q*4+0]=v.x; h1r[q*4+1]=v.y; h1r[q*4+2]=v.z; h1r[q*4+3]=v.w;
        }
    }
    hos[tid] = ho[((size_t)b*512 + i0)*32 + tid];
    if (tid < 32) wps[tid] = wphi[tid];
    if (tid < 128) webs[tid] = web[tid];
#pragma unroll
    for (int idx = tid; idx < 4096; idx += 512) {
        int hh = idx >> 5, d = idx & 31;
        wews[hh*33 + d] = wew[idx];
    }
    __syncthreads();

    for (int ii = 0; ii < 16; ii++) {
        float s = 0.f;
        const float* hoi = hos + ii*32;
        float2* wr2 = (float2*)(work + tid*34);
#pragma unroll
        for (int d2 = 0; d2 < 16; d2++) {
            float t0 = tanh_approx(hoi[2*d2]   + h1r[2*d2]);
            float t1 = tanh_approx(hoi[2*d2+1] + h1r[2*d2+1]);
            s = fmaf(wps[2*d2],   t0, s);
            s = fmaf(wps[2*d2+1], t1, s);
            wr2[d2] = make_float2(t0, t1);
        }
        float e = __expf(s);
        float es = e;
#pragma unroll
        for (int o = 16; o; o >>= 1) es += __shfl_xor_sync(0xffffffffu, es, o);
        if (lane == 0) part[w] = es;
        ss[tid] = e;
        __syncthreads();
        float tot = part[0];
#pragma unroll
        for (int q = 1; q < 16; q++) tot += part[q];
        float inv = 1.0f / tot;
        alpha[((size_t)(b*512 + i0 + ii))*512 + tid] = e * inv;
        {
            float acc = 0.f;
            const float* base = work + (w*32)*34 + lane;
            const float* eb = ss + w*32;
#pragma unroll
            for (int k = 0; k < 32; k++) acc = fmaf(eb[k], base[k*34], acc);
            cpart[w*33 + lane] = acc;
        }
        __syncthreads();
        if (tid < 32) {
            float c = 0.f;
#pragma unroll
            for (int q = 0; q < 16; q++) c += cpart[q*33 + tid];
            ctxa[ii*32 + tid] = c * inv;
        }
    }
    __syncthreads();

#pragma unroll
    for (int r = 0; r < 4; r++) {
        int o = tid + r*512;
        int ii = o >> 7, hh = o & 127;
        size_t row = (size_t)b*512 + i0 + ii;
        float v = XA[row*128 + hh] + XAC[row*128 + hh] + webs[hh];
        const float* cw = wews + hh*33;
        const float* cx = ctxa + ii*32;
#pragma unroll
        for (int d = 0; d < 32; d++) v = fmaf(cx[d], cw[d], v);
        bar[row*128 + hh] = v;
    }
}

// ---------------- batched NN GEMM accumulate (FFMA2 inner) --------------------
__global__ __launch_bounds__(256, 2) void gemm_nn_acc(
    const float* __restrict__ al, const float* __restrict__ Bx, float* __restrict__ C)
{
    __shared__ float As[2][32][68];
    __shared__ float Bs[2][32][68];
    int b = blockIdx.z, m0 = blockIdx.x*64, n0 = blockIdx.y*64;
    int tid = threadIdx.x, tx = tid & 15, ty = tid >> 4;
    const float* Ab = al + (size_t)b*512*512;
    const float* Bb = Bx + (size_t)b*512*128;
    unsigned long long accp[4][2];
#pragma unroll
    for (int r = 0; r < 4; r++) { accp[r][0] = 0ull; accp[r][1] = 0ull; }

    float4 av[2], bv[2];
    auto prefetch = [&](int k0) {
#pragma unroll
        for (int i = 0; i < 2; i++) {
            int idx = tid + i*256;
            int mm = idx >> 3, q = idx & 7;
            av[i] = *(const float4*)(Ab + (size_t)(m0+mm)*512 + k0 + q*4);
        }
#pragma unroll
        for (int i = 0; i < 2; i++) {
            int idx = tid + i*256;
            int kk = idx >> 4, q = idx & 15;
            bv[i] = *(const float4*)(Bb + (size_t)(k0+kk)*128 + n0 + q*4);
        }
    };
    auto stash = [&](int buf) {
#pragma unroll
        for (int i = 0; i < 2; i++) {
            int idx = tid + i*256;
            int mm = idx >> 3, q = idx & 7;
            As[buf][q*4+0][mm]=av[i].x; As[buf][q*4+1][mm]=av[i].y;
            As[buf][q*4+2][mm]=av[i].z; As[buf][q*4+3][mm]=av[i].w;
        }
#pragma unroll
        for (int i = 0; i < 2; i++) {
            int idx = tid + i*256;
            int kk = idx >> 4, q = idx & 15;
            *(float4*)&Bs[buf][kk][q*4] = bv[i];
        }
    };

    prefetch(0);
    stash(0);
    __syncthreads();
    for (int kt = 0; kt < 16; kt++) {
        int buf = kt & 1;
        if (kt + 1 < 16) prefetch((kt + 1) << 5);
#pragma unroll
        for (int k = 0; k < 32; k++) {
            float4 a = *(const float4*)&As[buf][k][ty*4];
            ulonglong2 wb = *(const ulonglong2*)&Bs[buf][k][tx*4];
            unsigned long long pa[4];
            pa[0] = pack2(a.x, a.x); pa[1] = pack2(a.y, a.y);
            pa[2] = pack2(a.z, a.z); pa[3] = pack2(a.w, a.w);
#pragma unroll
            for (int r = 0; r < 4; r++) {
                accp[r][0] = ffma2(pa[r], wb.x, accp[r][0]);
                accp[r][1] = ffma2(pa[r], wb.y, accp[r][1]);
            }
        }
        if (kt + 1 < 16) {
            stash(buf ^ 1);
            __syncthreads();
        }
    }
    float* Cb = C + (size_t)b*512*128;
#pragma unroll
    for (int r = 0; r < 4; r++)
#pragma unroll
        for (int cp = 0; cp < 2; cp++) {
            float2 v = unpack2(accp[r][cp]);
            size_t base = (size_t)(m0+ty*4+r)*128 + n0 + tx*4 + cp*2;
            Cb[base]     += v.x;
            Cb[base + 1] += v.y;
        }
}

// ---------------- SE block ---------------------------------------------------
__global__ __launch_bounds__(128) void se_kernel(
    const float* __restrict__ bar, const float* __restrict__ w1,
    const float* __restrict__ b1, const float* __restrict__ w2,
    const float* __restrict__ b2, float* __restrict__ y2)
{
    __shared__ float pooled[128];
    __shared__ float y1s[32];
    int b = blockIdx.x, tid = threadIdx.x;
    const float* base = bar + (size_t)(b << 9)*128 + tid;
    float p = 0.f;
#pragma unroll 8
    for (int n = 0; n < 512; n++) p += base[n*128];
    pooled[tid] = p;
    __syncthreads();
    if (tid < 32) {
        float v = b1[tid];
        const float* wr = w1 + tid*128;
#pragma unroll 8
        for (int h = 0; h < 128; h++) v = fmaf(pooled[h], wr[h], v);
        y1s[tid] = fmaxf(v, 0.f);
    }
    __syncthreads();
    float v = b2[tid];
    const float* wr = w2 + tid*32;
#pragma unroll
    for (int r = 0; r < 32; r++) v = fmaf(y1s[r], wr[r], v);
    y2[b*128 + tid] = __fdividef(1.0f, 1.0f + __expf(-v));
}

// ---------------- head2: out[4096,3] -----------------------------------------
__global__ __launch_bounds__(192) void head2_kernel(
    const float* __restrict__ Hin, const float* __restrict__ W,
    const float* __restrict__ bias, float* __restrict__ out)
{
    __shared__ float Hs[64][68];
    __shared__ float Ws3[192];
    __shared__ float bs[3];
    int tid = threadIdx.x, r0 = blockIdx.x*64;
    for (int idx = tid; idx < 64*16; idx += 192) {
        int m2 = idx >> 4, q = idx & 15;
        *(float4*)&Hs[m2][q*4] = *(const float4*)(Hin + (size_t)(r0+m2)*64 + q*4);
    }
    if (tid < 192) Ws3[tid] = W[tid];
    if (tid < 3) bs[tid] = bias[tid];
    __syncthreads();
    int r = tid/3, o = tid%3;
    float acc = bs[o];
#pragma unroll 8
    for (int k = 0; k < 64; k++) acc = fmaf(Hs[r][k], Ws3[o*64+k], acc);
    out[(size_t)(r0+r)*3 + o] = acc;
}

// ---------------- host orchestration ----------------------------------------
extern "C" void kernel_launch(void* const* d_in, const int* in_sizes, int n_in,
                              void* d_out, int out_size) {
    const float* X       = (const float*)d_in[0];
    const float* A       = (const float*)d_in[1];
    const float* Ac      = (const float*)d_in[2];
    const float* embed_w = (const float*)d_in[3];
    const float* embed_b = (const float*)d_in[4];
    const float* topo_eps= (const float*)d_in[5];
    const float* topo_w  = (const float*)d_in[6];
    const float* topo_b  = (const float*)d_in[7];
    const float* theta   = (const float*)d_in[8];
    const float* gin_eps = (const float*)d_in[9];
    const float* gin_w   = (const float*)d_in[10];
    const float* gin_b   = (const float*)d_in[11];
    const float* wo      = (const float*)d_in[12];
    const float* w1      = (const float*)d_in[13];
    const float* wphi    = (const float*)d_in[14];
    const float* wy_w    = (const float*)d_in[15];
    const float* wy_b    = (const float*)d_in[16];
    const float* we_w    = (const float*)d_in[17];
    const float* we_b    = (const float*)d_in[18];
    const float* lin1_w  = (const float*)d_in[19];
    const float* lin1_b  = (const float*)d_in[20];
    const float* lin2_w  = (const float*)d_in[21];
    const float* lin2_b  = (const float*)d_in[22];
    const float* mlp_w   = (const float*)d_in[23];
    const float* mlp_b   = (const float*)d_in[24];
    const float* head1_w = (const float*)d_in[25];
    const float* head1_b = (const float*)d_in[26];
    const float* head2_w = (const float*)d_in[27];
    const float* head2_b = (const float*)d_in[28];
    float* out = (float*)d_out;

    float* S = nullptr;
    cudaGetSymbolAddress((void**)&S, g_scratch);
    const size_t BIG = 524288;
    float* Xh    = S;
    float* Xp    = S + 1*BIG;
    float* aggA  = S + 2*BIG;
    float* aggAc = S + 3*BIG;
    float* XAb   = S + 4*BIG;
    float* XACb  = S + 5*BIG;
    float* Xy    = S + 6*BIG;
    float* bar   = S + 7*BIG;
    float* hob   = S + 8*BIG;
    float* h1b   = hob + 131072;
    float* alphab= h1b + 131072;
    float* y2b   = alphab + 2097152;
    float* h64   = y2b + 1024;

    const int ATTN_SMEM = (17408 + 512 + 32 + 16 + 528 + 512 + 4224 + 128 + 512) * 4; // 95488
    const int GEMM_SMEM = (2*32*68 + 2*32*132) * 4;   // 51200
    const int HALF_SMEM = (2*32*36 + 2*32*132) * 4;   // 43008
    cudaFuncSetAttribute(attn_kernel, cudaFuncAttributeMaxDynamicSharedMemorySize, ATTN_SMEM);
    cudaFuncSetAttribute(gemm_multi, cudaFuncAttributeMaxDynamicSharedMemorySize, GEMM_SMEM);
    cudaFuncSetAttribute(gemm_half, cudaFuncAttributeMaxDynamicSharedMemorySize, HALF_SMEM);

    build_adj<<<dim3(4096, 2), 128>>>(A, Ac);

    gemm_half<<<128, 256, HALF_SMEM>>>(GJob{X, embed_w, embed_b, Xh, nullptr, 64, 128, 0});
    gin_agg<<<dim3(1024, 2), 128>>>(Xh, aggA, aggAc, topo_eps, topo_eps);
    {
        GJobs js{};
        js.j[0] = GJob{aggA,  topo_w, topo_b, XAb,  nullptr, 128, 128, 1};
        js.j[1] = GJob{aggAc, topo_w, topo_b, XACb, nullptr, 128, 128, 1};
        gemm_multi<<<dim3(64, 2), 256, GEMM_SMEM>>>(js);
    }
    topo_combine<<<2048, 256>>>(Xh, XAb, XACb, theta, Xp);

    for (int l = 0; l < 3; l++) {
        gin_agg<<<dim3(1024, 2), 128>>>(Xp, aggA, aggAc,
                                        gin_eps + l*2, gin_eps + l*2 + 1);
        {
            GJobs js{};
            js.j[0] = GJob{aggA,  gin_w + (size_t)(l*2+0)*16384, gin_b + (l*2+0)*128, XAb,  nullptr, 128, 128, 1};
            js.j[1] = GJob{aggAc, gin_w + (size_t)(l*2+1)*16384, gin_b + (l*2+1)*128, XACb, nullptr, 128, 128, 1};
            js.j[2] = GJob{Xp, wy_w + (size_t)l*16384, wy_b + l*128, Xy, nullptr, 128, 128, 0};
            js.j[3] = GJob{Xp, wo + (size_t)l*4096, nullptr, hob, nullptr, 128, 32, 0};
            js.j[4] = GJob{Xp, w1 + (size_t)l*4096, nullptr, h1b, nullptr, 128, 32, 0};
            gemm_multi<<<dim3(64, 5), 256, GEMM_SMEM>>>(js);
        }
        attn_kernel<<<256, 512, ATTN_SMEM>>>(hob, h1b, wphi + l*32, XAb, XACb,
                                             we_w + (size_t)l*4096, we_b + l*128,
                                             alphab, bar);
        gemm_nn_acc<<<dim3(8, 2, 8), 256>>>(alphab, Xy, bar);
        se_kernel<<<8, 128>>>(bar, lin1_w + (size_t)l*4096, lin1_b + l*32,
                              lin2_w + (size_t)l*4096, lin2_b + l*128, y2b);
        gemm_half<<<128, 256, HALF_SMEM>>>(GJob{bar, mlp_w + (size_t)l*16384, mlp_b + l*128, Xp, y2b, 128, 128, 4});
    }
    gemm_half<<<128, 256, HALF_SMEM>>>(GJob{Xp, head1_w, head1_b, h64, nullptr, 128, 64, 1});
    head2_kernel<<<64, 192>>>(h64, head2_w, head2_b, out);
}